// round 1
// baseline (speedup 1.0000x reference)
#include <cuda_runtime.h>

#define D_MODEL 768
#define NH      12
#define HEADD   64
#define BATCH   2
#define SEQ     2048
#define M_TOK   (BATCH*SEQ)   // 4096

// ---- scratch (device globals; no allocations allowed) ----
__device__ float g_q[(size_t)BATCH*NH*SEQ*HEADD];
__device__ float g_k[(size_t)BATCH*NH*SEQ*HEADD];
__device__ float g_v[(size_t)BATCH*NH*SEQ*HEADD];
__device__ float g_o[(size_t)M_TOK*D_MODEL];

// ============================================================
// SGEMM: C[m][n] = sum_k A[m][k] * B[n][k] + bias[n]
// BM=BN=128, BK=8, 256 threads, 8x8 per thread.
// MODE 0: scatter into g_q/g_k/g_v (QKV projection)
// MODE 1: plain store into C
// ============================================================
template<int MODE>
__global__ __launch_bounds__(256)
void sgemm_kernel(const float* __restrict__ A,
                  const float* __restrict__ Bm,
                  const float* __restrict__ bias,
                  float* __restrict__ C,
                  int M, int N, int K)
{
    __shared__ float As[8][128];
    __shared__ float Bs[8][128];

    const int tid  = threadIdx.x;
    const int row0 = blockIdx.y * 128;
    const int col0 = blockIdx.x * 128;
    const int lr   = tid >> 1;          // 0..127
    const int lk   = (tid & 1) << 2;    // 0 or 4
    const int tx   = tid & 15;
    const int ty   = tid >> 4;

    const float* Ap = A  + (size_t)(row0 + lr) * K + lk;
    const float* Bp = Bm + (size_t)(col0 + lr) * K + lk;

    float acc[8][8] = {};

    for (int k0 = 0; k0 < K; k0 += 8) {
        float4 av = *(const float4*)(Ap + k0);
        float4 bv = *(const float4*)(Bp + k0);
        __syncthreads();
        As[lk+0][lr] = av.x; As[lk+1][lr] = av.y;
        As[lk+2][lr] = av.z; As[lk+3][lr] = av.w;
        Bs[lk+0][lr] = bv.x; Bs[lk+1][lr] = bv.y;
        Bs[lk+2][lr] = bv.z; Bs[lk+3][lr] = bv.w;
        __syncthreads();
        #pragma unroll
        for (int kk = 0; kk < 8; kk++) {
            float a[8], b[8];
            *(float4*)&a[0] = *(const float4*)&As[kk][ty*8];
            *(float4*)&a[4] = *(const float4*)&As[kk][ty*8+4];
            *(float4*)&b[0] = *(const float4*)&Bs[kk][tx*8];
            *(float4*)&b[4] = *(const float4*)&Bs[kk][tx*8+4];
            #pragma unroll
            for (int i = 0; i < 8; i++)
                #pragma unroll
                for (int j = 0; j < 8; j++)
                    acc[i][j] = fmaf(a[i], b[j], acc[i][j]);
        }
    }

    if (MODE == 0) {
        // scatter QKV: f in [0,2304). which = f/768, c = f%768, h=c/64, d=c%64
        #pragma unroll
        for (int i = 0; i < 8; i++) {
            int m  = row0 + ty*8 + i;
            int bb = m >> 11;          // m / SEQ
            int t  = m & (SEQ-1);
            #pragma unroll
            for (int jv = 0; jv < 8; jv += 4) {
                int f = col0 + tx*8 + jv;
                float4 val;
                val.x = acc[i][jv+0] + bias[f+0];
                val.y = acc[i][jv+1] + bias[f+1];
                val.z = acc[i][jv+2] + bias[f+2];
                val.w = acc[i][jv+3] + bias[f+3];
                int which = f / D_MODEL;
                int c = f - which * D_MODEL;
                int h = c >> 6;
                int d = c & 63;
                float* dst = (which == 0) ? g_q : ((which == 1) ? g_k : g_v);
                size_t idx = (((size_t)(bb*NH + h))*SEQ + t)*HEADD + d;
                *(float4*)&dst[idx] = val;
            }
        }
    } else {
        #pragma unroll
        for (int i = 0; i < 8; i++) {
            int m = row0 + ty*8 + i;
            #pragma unroll
            for (int jv = 0; jv < 8; jv += 4) {
                int f = col0 + tx*8 + jv;
                float4 val;
                val.x = acc[i][jv+0] + bias[f+0];
                val.y = acc[i][jv+1] + bias[f+1];
                val.z = acc[i][jv+2] + bias[f+2];
                val.w = acc[i][jv+3] + bias[f+3];
                *(float4*)&C[(size_t)m*N + f] = val;
            }
        }
    }
}

// ============================================================
// Flash attention (causal), fp32.
// Grid: (SEQ/64, BATCH*NH), 256 threads (16x16), per-thread 4x4.
// Q/K tiles stored transposed [d][i] with XOR swizzle (conflict-free
// float4 reads along the common dim). P overwrites the K buffer.
// ============================================================
__device__ __forceinline__ int tswz(int d, int i) {
    // word index for swizzled 64x64 tile, "row" = common dim d
    return d*64 + ((((i >> 2) ^ (d & 15)) << 2) | (i & 3));
}

__global__ __launch_bounds__(256)
void attn_kernel()
{
    __shared__ float Qs[64*64];
    __shared__ float Ks[64*64];   // K tile, later reused as P^T
    __shared__ float Vs[64*64];   // plain row-major [j][d]

    const int tid = threadIdx.x;
    const int tx  = tid & 15;
    const int ty  = tid >> 4;
    const int bh  = blockIdx.y;           // b*NH + h
    const int qt  = blockIdx.x;
    const int q0  = qt * 64;

    const float* Qg = g_q + (size_t)bh * SEQ * HEADD;
    const float* Kg = g_k + (size_t)bh * SEQ * HEADD;
    const float* Vg = g_v + (size_t)bh * SEQ * HEADD;

    const float scale = 0.125f;  // 1/sqrt(64)

    // load Q tile, transposed + swizzled + pre-scaled
    #pragma unroll
    for (int it = 0; it < 4; it++) {
        int lin = tid + it*256;
        int r   = lin >> 4;          // 0..63 (query row within tile)
        int d0  = (lin & 15) << 2;
        float4 v = *(const float4*)(Qg + (size_t)(q0 + r)*HEADD + d0);
        Qs[tswz(d0+0, r)] = v.x * scale;
        Qs[tswz(d0+1, r)] = v.y * scale;
        Qs[tswz(d0+2, r)] = v.z * scale;
        Qs[tswz(d0+3, r)] = v.w * scale;
    }

    float m_[4], l_[4], o_[4][4];
    #pragma unroll
    for (int i = 0; i < 4; i++) {
        m_[i] = -1e30f; l_[i] = 0.f;
        #pragma unroll
        for (int j = 0; j < 4; j++) o_[i][j] = 0.f;
    }

    for (int kt = 0; kt <= qt; kt++) {
        const int kc = kt * 64;

        // prefetch K/V into registers (overlaps prior iteration drain)
        float4 kf[4], vf[4];
        #pragma unroll
        for (int it = 0; it < 4; it++) {
            int lin = tid + it*256;
            int r   = lin >> 4;
            int d0  = (lin & 15) << 2;
            kf[it] = *(const float4*)(Kg + (size_t)(kc + r)*HEADD + d0);
            vf[it] = *(const float4*)(Vg + (size_t)(kc + r)*HEADD + d0);
        }
        __syncthreads();   // prior P*V reads of Ks/Vs complete (and Q load on it 0)
        #pragma unroll
        for (int it = 0; it < 4; it++) {
            int lin = tid + it*256;
            int r   = lin >> 4;
            int d0  = (lin & 15) << 2;
            Ks[tswz(d0+0, r)] = kf[it].x;
            Ks[tswz(d0+1, r)] = kf[it].y;
            Ks[tswz(d0+2, r)] = kf[it].z;
            Ks[tswz(d0+3, r)] = kf[it].w;
            *(float4*)&Vs[r*64 + d0] = vf[it];
        }
        __syncthreads();

        // S = Q K^T (4x4 per thread)
        float s[4][4] = {};
        #pragma unroll 8
        for (int d = 0; d < 64; d++) {
            float4 a = *(const float4*)(Qs + d*64 + ((ty ^ (d & 15)) << 2));
            float4 b = *(const float4*)(Ks + d*64 + ((tx ^ (d & 15)) << 2));
            s[0][0] = fmaf(a.x, b.x, s[0][0]); s[0][1] = fmaf(a.x, b.y, s[0][1]);
            s[0][2] = fmaf(a.x, b.z, s[0][2]); s[0][3] = fmaf(a.x, b.w, s[0][3]);
            s[1][0] = fmaf(a.y, b.x, s[1][0]); s[1][1] = fmaf(a.y, b.y, s[1][1]);
            s[1][2] = fmaf(a.y, b.z, s[1][2]); s[1][3] = fmaf(a.y, b.w, s[1][3]);
            s[2][0] = fmaf(a.z, b.x, s[2][0]); s[2][1] = fmaf(a.z, b.y, s[2][1]);
            s[2][2] = fmaf(a.z, b.z, s[2][2]); s[2][3] = fmaf(a.z, b.w, s[2][3]);
            s[3][0] = fmaf(a.w, b.x, s[3][0]); s[3][1] = fmaf(a.w, b.y, s[3][1]);
            s[3][2] = fmaf(a.w, b.z, s[3][2]); s[3][3] = fmaf(a.w, b.w, s[3][3]);
        }

        // causal mask on the diagonal tile
        if (kt == qt) {
            #pragma unroll
            for (int ii = 0; ii < 4; ii++)
                #pragma unroll
                for (int jj = 0; jj < 4; jj++)
                    if ((tx<<2) + jj > (ty<<2) + ii) s[ii][jj] = -1e30f;
        }

        // online softmax (per row; reduce across tx = 16 lanes)
        #pragma unroll
        for (int ii = 0; ii < 4; ii++) {
            float rm = fmaxf(fmaxf(s[ii][0], s[ii][1]), fmaxf(s[ii][2], s[ii][3]));
            rm = fmaxf(rm, __shfl_xor_sync(0xffffffffu, rm, 8));
            rm = fmaxf(rm, __shfl_xor_sync(0xffffffffu, rm, 4));
            rm = fmaxf(rm, __shfl_xor_sync(0xffffffffu, rm, 2));
            rm = fmaxf(rm, __shfl_xor_sync(0xffffffffu, rm, 1));
            float mn   = fmaxf(m_[ii], rm);
            float corr = __expf(m_[ii] - mn);
            float rs = 0.f;
            #pragma unroll
            for (int jj = 0; jj < 4; jj++) {
                float p = __expf(s[ii][jj] - mn);
                s[ii][jj] = p;
                rs += p;
            }
            rs += __shfl_xor_sync(0xffffffffu, rs, 8);
            rs += __shfl_xor_sync(0xffffffffu, rs, 4);
            rs += __shfl_xor_sync(0xffffffffu, rs, 2);
            rs += __shfl_xor_sync(0xffffffffu, rs, 1);
            l_[ii] = l_[ii] * corr + rs;
            m_[ii] = mn;
            #pragma unroll
            for (int jj = 0; jj < 4; jj++) o_[ii][jj] *= corr;
        }

        __syncthreads();  // all S reads of Ks done
        // store P^T into Ks buffer: layout [j][i], swizzled
        #pragma unroll
        for (int jj = 0; jj < 4; jj++) {
            int j = (tx<<2) + jj;
            #pragma unroll
            for (int ii = 0; ii < 4; ii++) {
                Ks[j*64 + ((ty ^ (j & 15)) << 2) + ii] = s[ii][jj];
            }
        }
        __syncthreads();

        // O += P V
        #pragma unroll 4
        for (int j = 0; j < 64; j++) {
            float4 p = *(const float4*)(Ks + j*64 + ((ty ^ (j & 15)) << 2));
            float4 v = *(const float4*)(Vs + j*64 + (tx << 2));
            o_[0][0] = fmaf(p.x, v.x, o_[0][0]); o_[0][1] = fmaf(p.x, v.y, o_[0][1]);
            o_[0][2] = fmaf(p.x, v.z, o_[0][2]); o_[0][3] = fmaf(p.x, v.w, o_[0][3]);
            o_[1][0] = fmaf(p.y, v.x, o_[1][0]); o_[1][1] = fmaf(p.y, v.y, o_[1][1]);
            o_[1][2] = fmaf(p.y, v.z, o_[1][2]); o_[1][3] = fmaf(p.y, v.w, o_[1][3]);
            o_[2][0] = fmaf(p.z, v.x, o_[2][0]); o_[2][1] = fmaf(p.z, v.y, o_[2][1]);
            o_[2][2] = fmaf(p.z, v.z, o_[2][2]); o_[2][3] = fmaf(p.z, v.w, o_[2][3]);
            o_[3][0] = fmaf(p.w, v.x, o_[3][0]); o_[3][1] = fmaf(p.w, v.y, o_[3][1]);
            o_[3][2] = fmaf(p.w, v.z, o_[3][2]); o_[3][3] = fmaf(p.w, v.w, o_[3][3]);
        }
    }

    // epilogue: normalize and write O to (b, t, h*64+d) layout
    const int b = bh / NH;
    const int h = bh - b * NH;
    #pragma unroll
    for (int ii = 0; ii < 4; ii++) {
        float inv = 1.f / l_[ii];
        int t = q0 + (ty<<2) + ii;
        float4 val;
        val.x = o_[ii][0] * inv;
        val.y = o_[ii][1] * inv;
        val.z = o_[ii][2] * inv;
        val.w = o_[ii][3] * inv;
        size_t idx = ((size_t)(b*SEQ + t))*D_MODEL + h*HEADD + (tx<<2);
        *(float4*)&g_o[idx] = val;
    }
}

// ============================================================
extern "C" void kernel_launch(void* const* d_in, const int* in_sizes, int n_in,
                              void* d_out, int out_size)
{
    const float* x  = (const float*)d_in[0];   // (B,T,768)
    const float* W1 = (const float*)d_in[1];   // (2304,768)
    const float* b1 = (const float*)d_in[2];   // (2304,)
    const float* W2 = (const float*)d_in[3];   // (768,768)
    const float* b2 = (const float*)d_in[4];   // (768,)
    float* out = (float*)d_out;

    float* oq;
    cudaGetSymbolAddress((void**)&oq, g_o);

    // 1) QKV projection: Y[4096,2304] = x @ W1^T + b1, scattered to q/k/v
    {
        dim3 grid(3*D_MODEL/128, M_TOK/128);   // (18, 32)
        sgemm_kernel<0><<<grid, 256>>>(x, W1, b1, nullptr, M_TOK, 3*D_MODEL, D_MODEL);
    }
    // 2) causal attention
    {
        dim3 grid(SEQ/64, BATCH*NH);           // (32, 24)
        attn_kernel<<<grid, 256>>>();
    }
    // 3) output projection: out = O @ W2^T + b2
    {
        dim3 grid(D_MODEL/128, M_TOK/128);     // (6, 32)
        sgemm_kernel<1><<<grid, 256>>>(oq, W2, b2, out, M_TOK, D_MODEL, D_MODEL);
    }
}

// round 3
// speedup vs baseline: 1.4322x; 1.4322x over previous
#include <cuda_runtime.h>
#include <cuda_bf16.h>
#include <cstdint>

#define D_MODEL 768
#define NH      12
#define HEADD   64
#define BATCH   2
#define SEQ     2048
#define M_TOK   (BATCH*SEQ)   // 4096
#define N_QKV   (3*D_MODEL)   // 2304

// ============================================================
// helpers
// ============================================================
__device__ __forceinline__ uint32_t smem_u32(const void* p) {
    uint32_t a;
    asm("{ .reg .u64 t; cvta.to.shared.u64 t, %1; cvt.u32.u64 %0, t; }" : "=r"(a) : "l"(p));
    return a;
}

__device__ __forceinline__ void ldsm4(uint32_t* r, uint32_t addr) {
    asm volatile("ldmatrix.sync.aligned.m8n8.x4.shared.b16 {%0,%1,%2,%3}, [%4];"
        : "=r"(r[0]), "=r"(r[1]), "=r"(r[2]), "=r"(r[3]) : "r"(addr));
}

__device__ __forceinline__ void mma16816(float* c, const uint32_t* a, const uint32_t* b) {
    asm volatile(
        "mma.sync.aligned.m16n8k16.row.col.f32.bf16.bf16.f32 "
        "{%0,%1,%2,%3}, {%4,%5,%6,%7}, {%8,%9}, {%0,%1,%2,%3};"
        : "+f"(c[0]), "+f"(c[1]), "+f"(c[2]), "+f"(c[3])
        : "r"(a[0]), "r"(a[1]), "r"(a[2]), "r"(a[3]), "r"(b[0]), "r"(b[1]));
}

#define SWZ(off) ((off) ^ (((off) >> 3) & 0x70))

// ---- scratch (device globals; no allocations allowed) ----
__device__ float g_q[(size_t)BATCH*NH*SEQ*HEADD];
__device__ float g_k[(size_t)BATCH*NH*SEQ*HEADD];
__device__ float g_v[(size_t)BATCH*NH*SEQ*HEADD];
__device__ float g_o[(size_t)M_TOK*D_MODEL];

__device__ __align__(16) __nv_bfloat16 g_xh[(size_t)M_TOK*D_MODEL];
__device__ __align__(16) __nv_bfloat16 g_xl[(size_t)M_TOK*D_MODEL];
__device__ __align__(16) __nv_bfloat16 g_w1h[(size_t)N_QKV*D_MODEL];
__device__ __align__(16) __nv_bfloat16 g_w1l[(size_t)N_QKV*D_MODEL];
__device__ __align__(16) __nv_bfloat16 g_w2h[(size_t)D_MODEL*D_MODEL];
__device__ __align__(16) __nv_bfloat16 g_w2l[(size_t)D_MODEL*D_MODEL];
__device__ __align__(16) __nv_bfloat16 g_oh[(size_t)M_TOK*D_MODEL];
__device__ __align__(16) __nv_bfloat16 g_ol[(size_t)M_TOK*D_MODEL];

// ============================================================
// fp32 -> (bf16 hi, bf16 lo) split
// ============================================================
__global__ __launch_bounds__(256)
void convert_split(const float* __restrict__ src,
                   __nv_bfloat16* __restrict__ hi, __nv_bfloat16* __restrict__ lo, int n)
{
    int i = (blockIdx.x * blockDim.x + threadIdx.x) * 4;
    if (i >= n) return;
    float4 v = *(const float4*)(src + i);
    float f[4] = {v.x, v.y, v.z, v.w};
    __nv_bfloat16 h[4], l[4];
    #pragma unroll
    for (int j = 0; j < 4; j++) {
        h[j] = __float2bfloat16(f[j]);
        l[j] = __float2bfloat16(f[j] - __bfloat162float(h[j]));
    }
    *(__nv_bfloat162*)(hi + i)     = __halves2bfloat162(h[0], h[1]);
    *(__nv_bfloat162*)(hi + i + 2) = __halves2bfloat162(h[2], h[3]);
    *(__nv_bfloat162*)(lo + i)     = __halves2bfloat162(l[0], l[1]);
    *(__nv_bfloat162*)(lo + i + 2) = __halves2bfloat162(l[2], l[3]);
}

// ============================================================
// bf16x3 GEMM via mma.sync: C[m][n] = sum_k A[m][k]*B[n][k] + bias[n]
// CTA tile 128x128, 256 thr (8 warps, warp tile 64x32), K chunks of 64,
// 2-stage cp.async pipeline, SW128-swizzled smem + ldmatrix.
// MODE 0: scatter to g_q/g_k/g_v.  MODE 1: plain store to C.
// ============================================================
static constexpr int GBK     = 64;
static constexpr int NCH     = D_MODEL / GBK;    // 12
static constexpr int TILE_B  = 128 * 128;        // 16 KB: 128 rows x 128B
static constexpr int STAGE_B = 4 * TILE_B;       // 64 KB: Ah, Al, Bh, Bl
static constexpr int SMEM_GEMM = 2 * STAGE_B;    // 128 KB

__device__ __forceinline__ void load_tile_async(uint32_t smem_tile, const __nv_bfloat16* g,
                                                int row0, int k0, int tid)
{
    #pragma unroll
    for (int i = 0; i < 4; i++) {
        int u  = tid + i * 256;        // 0..1023
        int r  = u >> 3;               // 0..127
        int cu = u & 7;                // 16B unit within 128B row
        uint32_t dst = smem_tile + SWZ((uint32_t)(r * 128 + cu * 16));
        const void* src = g + (size_t)(row0 + r) * D_MODEL + k0 + cu * 8;
        asm volatile("cp.async.cg.shared.global [%0], [%1], 16;" :: "r"(dst), "l"(src) : "memory");
    }
}

template<int MODE>
__global__ __launch_bounds__(256, 1)
void gemm_mma(const __nv_bfloat16* __restrict__ Ah, const __nv_bfloat16* __restrict__ Al,
              const __nv_bfloat16* __restrict__ Bh, const __nv_bfloat16* __restrict__ Bl,
              const float* __restrict__ bias, float* __restrict__ C, int N)
{
    extern __shared__ __align__(1024) char smem[];
    const uint32_t sb = smem_u32(smem);
    const int tid  = threadIdx.x;
    const int wid  = tid >> 5;
    const int lane = tid & 31;
    const int wm   = wid & 1;        // 2 m-subtiles of 64
    const int wn   = wid >> 1;       // 4 n-subtiles of 32
    const int row0 = blockIdx.y * 128;
    const int col0 = blockIdx.x * 128;

    float acc[4][4][4] = {};

    // per-thread ldmatrix geometry
    const int aRow = wm * 64 + (lane & 15);
    const uint32_t xr = (uint32_t)((aRow & 7) << 4);
    const int aHalf = lane >> 4;                       // 0/1 -> k+0 / k+8
    const int bN = wn * 32 + (lane & 7) + ((lane >> 4) << 3);
    const uint32_t xn = (uint32_t)((lane & 7) << 4);
    const int bKb = ((lane >> 3) & 1) * 16;            // byte 0 / 16 -> k+0 / k+8

    // prologue
    auto stage_addr = [&](int s) { return sb + (uint32_t)s * STAGE_B; };
    {
        uint32_t st = stage_addr(0);
        load_tile_async(st + 0*TILE_B, Ah, row0, 0, tid);
        load_tile_async(st + 1*TILE_B, Al, row0, 0, tid);
        load_tile_async(st + 2*TILE_B, Bh, col0, 0, tid);
        load_tile_async(st + 3*TILE_B, Bl, col0, 0, tid);
        asm volatile("cp.async.commit_group;" ::: "memory");
        st = stage_addr(1);
        load_tile_async(st + 0*TILE_B, Ah, row0, GBK, tid);
        load_tile_async(st + 1*TILE_B, Al, row0, GBK, tid);
        load_tile_async(st + 2*TILE_B, Bh, col0, GBK, tid);
        load_tile_async(st + 3*TILE_B, Bl, col0, GBK, tid);
        asm volatile("cp.async.commit_group;" ::: "memory");
    }

    for (int c = 0; c < NCH; c++) {
        const int s = c & 1;
        if (c < NCH - 1) asm volatile("cp.async.wait_group 1;" ::: "memory");
        else             asm volatile("cp.async.wait_group 0;" ::: "memory");
        __syncthreads();

        const uint32_t st   = stage_addr(s);
        const uint32_t stAh = st;
        const uint32_t stAl = st + TILE_B;
        const uint32_t stBh = st + 2*TILE_B;
        const uint32_t stBl = st + 3*TILE_B;

        #pragma unroll
        for (int ks = 0; ks < 4; ks++) {
            const uint32_t aKx = (uint32_t)((ks*32 + aHalf*16)) ^ xr;
            const uint32_t bKx = (uint32_t)((ks*32 + bKb)) ^ xn;

            uint32_t Afh[4][4], Afl[4][4], Bfh[2][4], Bfl[2][4];
            #pragma unroll
            for (int mi = 0; mi < 4; mi++) {
                uint32_t off = (uint32_t)((aRow + mi*16) * 128) + aKx;
                ldsm4(Afh[mi], stAh + off);
                ldsm4(Afl[mi], stAl + off);
            }
            #pragma unroll
            for (int j2 = 0; j2 < 2; j2++) {
                uint32_t off = (uint32_t)((bN + j2*16) * 128) + bKx;
                ldsm4(Bfh[j2], stBh + off);
                ldsm4(Bfl[j2], stBl + off);
            }
            #pragma unroll
            for (int mi = 0; mi < 4; mi++) {
                #pragma unroll
                for (int nj = 0; nj < 4; nj++) {
                    const uint32_t* bh = &Bfh[nj >> 1][(nj & 1) * 2];
                    const uint32_t* bl = &Bfl[nj >> 1][(nj & 1) * 2];
                    mma16816(acc[mi][nj], Afh[mi], bh);
                    mma16816(acc[mi][nj], Afh[mi], bl);
                    mma16816(acc[mi][nj], Afl[mi], bh);
                }
            }
        }
        __syncthreads();

        if (c + 2 < NCH) {
            uint32_t st2 = stage_addr(s);
            int k0 = (c + 2) * GBK;
            load_tile_async(st2 + 0*TILE_B, Ah, row0, k0, tid);
            load_tile_async(st2 + 1*TILE_B, Al, row0, k0, tid);
            load_tile_async(st2 + 2*TILE_B, Bh, col0, k0, tid);
            load_tile_async(st2 + 3*TILE_B, Bl, col0, k0, tid);
            asm volatile("cp.async.commit_group;" ::: "memory");
        }
    }

    // epilogue
    #pragma unroll
    for (int mi = 0; mi < 4; mi++) {
        #pragma unroll
        for (int h2 = 0; h2 < 2; h2++) {
            const int m  = row0 + wm*64 + mi*16 + h2*8 + (lane >> 2);
            const int bb = m >> 11;
            const int t  = m & (SEQ - 1);
            #pragma unroll
            for (int nj = 0; nj < 4; nj++) {
                const int f = col0 + wn*32 + nj*8 + (lane & 3)*2;
                float2 v;
                v.x = acc[mi][nj][h2*2+0] + bias[f];
                v.y = acc[mi][nj][h2*2+1] + bias[f+1];
                if (MODE == 0) {
                    int which = (f >= 1536) ? 2 : (f >= 768 ? 1 : 0);
                    int cc = f - which * 768;
                    int h = cc >> 6, d = cc & 63;
                    float* base = (which == 0) ? g_q : ((which == 1) ? g_k : g_v);
                    *(float2*)&base[(((size_t)(bb*NH + h))*SEQ + t)*HEADD + d] = v;
                } else {
                    *(float2*)&C[(size_t)m * N + f] = v;
                }
            }
        }
    }
}

// ============================================================
// Flash attention (causal), fp32 SIMT, reversed qt order.
// ============================================================
__device__ __forceinline__ int tswz(int d, int i) {
    return d*64 + ((((i >> 2) ^ (d & 15)) << 2) | (i & 3));
}

__global__ __launch_bounds__(256)
void attn_kernel()
{
    __shared__ float Qs[64*64];
    __shared__ float Ks[64*64];
    __shared__ float Vs[64*64];

    const int tid = threadIdx.x;
    const int tx  = tid & 15;
    const int ty  = tid >> 4;
    const int bh  = blockIdx.y;
    const int qt  = gridDim.x - 1 - blockIdx.x;
    const int q0  = qt * 64;

    const float* Qg = g_q + (size_t)bh * SEQ * HEADD;
    const float* Kg = g_k + (size_t)bh * SEQ * HEADD;
    const float* Vg = g_v + (size_t)bh * SEQ * HEADD;

    const float scale = 0.125f;

    #pragma unroll
    for (int it = 0; it < 4; it++) {
        int lin = tid + it*256;
        int r   = lin >> 4;
        int d0  = (lin & 15) << 2;
        float4 v = *(const float4*)(Qg + (size_t)(q0 + r)*HEADD + d0);
        Qs[tswz(d0+0, r)] = v.x * scale;
        Qs[tswz(d0+1, r)] = v.y * scale;
        Qs[tswz(d0+2, r)] = v.z * scale;
        Qs[tswz(d0+3, r)] = v.w * scale;
    }

    float m_[4], l_[4], o_[4][4];
    #pragma unroll
    for (int i = 0; i < 4; i++) {
        m_[i] = -1e30f; l_[i] = 0.f;
        #pragma unroll
        for (int j = 0; j < 4; j++) o_[i][j] = 0.f;
    }

    for (int kt = 0; kt <= qt; kt++) {
        const int kc = kt * 64;

        float4 kf[4], vf[4];
        #pragma unroll
        for (int it = 0; it < 4; it++) {
            int lin = tid + it*256;
            int r   = lin >> 4;
            int d0  = (lin & 15) << 2;
            kf[it] = *(const float4*)(Kg + (size_t)(kc + r)*HEADD + d0);
            vf[it] = *(const float4*)(Vg + (size_t)(kc + r)*HEADD + d0);
        }
        __syncthreads();
        #pragma unroll
        for (int it = 0; it < 4; it++) {
            int lin = tid + it*256;
            int r   = lin >> 4;
            int d0  = (lin & 15) << 2;
            Ks[tswz(d0+0, r)] = kf[it].x;
            Ks[tswz(d0+1, r)] = kf[it].y;
            Ks[tswz(d0+2, r)] = kf[it].z;
            Ks[tswz(d0+3, r)] = kf[it].w;
            *(float4*)&Vs[r*64 + d0] = vf[it];
        }
        __syncthreads();

        float s[4][4] = {};
        #pragma unroll 8
        for (int d = 0; d < 64; d++) {
            float4 a = *(const float4*)(Qs + d*64 + ((ty ^ (d & 15)) << 2));
            float4 b = *(const float4*)(Ks + d*64 + ((tx ^ (d & 15)) << 2));
            s[0][0] = fmaf(a.x, b.x, s[0][0]); s[0][1] = fmaf(a.x, b.y, s[0][1]);
            s[0][2] = fmaf(a.x, b.z, s[0][2]); s[0][3] = fmaf(a.x, b.w, s[0][3]);
            s[1][0] = fmaf(a.y, b.x, s[1][0]); s[1][1] = fmaf(a.y, b.y, s[1][1]);
            s[1][2] = fmaf(a.y, b.z, s[1][2]); s[1][3] = fmaf(a.y, b.w, s[1][3]);
            s[2][0] = fmaf(a.z, b.x, s[2][0]); s[2][1] = fmaf(a.z, b.y, s[2][1]);
            s[2][2] = fmaf(a.z, b.z, s[2][2]); s[2][3] = fmaf(a.z, b.w, s[2][3]);
            s[3][0] = fmaf(a.w, b.x, s[3][0]); s[3][1] = fmaf(a.w, b.y, s[3][1]);
            s[3][2] = fmaf(a.w, b.z, s[3][2]); s[3][3] = fmaf(a.w, b.w, s[3][3]);
        }

        if (kt == qt) {
            #pragma unroll
            for (int ii = 0; ii < 4; ii++)
                #pragma unroll
                for (int jj = 0; jj < 4; jj++)
                    if ((tx<<2) + jj > (ty<<2) + ii) s[ii][jj] = -1e30f;
        }

        #pragma unroll
        for (int ii = 0; ii < 4; ii++) {
            float rm = fmaxf(fmaxf(s[ii][0], s[ii][1]), fmaxf(s[ii][2], s[ii][3]));
            rm = fmaxf(rm, __shfl_xor_sync(0xffffffffu, rm, 8));
            rm = fmaxf(rm, __shfl_xor_sync(0xffffffffu, rm, 4));
            rm = fmaxf(rm, __shfl_xor_sync(0xffffffffu, rm, 2));
            rm = fmaxf(rm, __shfl_xor_sync(0xffffffffu, rm, 1));
            float mn   = fmaxf(m_[ii], rm);
            float corr = __expf(m_[ii] - mn);
            float rs = 0.f;
            #pragma unroll
            for (int jj = 0; jj < 4; jj++) {
                float p = __expf(s[ii][jj] - mn);
                s[ii][jj] = p;
                rs += p;
            }
            rs += __shfl_xor_sync(0xffffffffu, rs, 8);
            rs += __shfl_xor_sync(0xffffffffu, rs, 4);
            rs += __shfl_xor_sync(0xffffffffu, rs, 2);
            rs += __shfl_xor_sync(0xffffffffu, rs, 1);
            l_[ii] = l_[ii] * corr + rs;
            m_[ii] = mn;
            #pragma unroll
            for (int jj = 0; jj < 4; jj++) o_[ii][jj] *= corr;
        }

        __syncthreads();
        #pragma unroll
        for (int jj = 0; jj < 4; jj++) {
            int j = (tx<<2) + jj;
            #pragma unroll
            for (int ii = 0; ii < 4; ii++) {
                Ks[j*64 + ((ty ^ (j & 15)) << 2) + ii] = s[ii][jj];
            }
        }
        __syncthreads();

        #pragma unroll 4
        for (int j = 0; j < 64; j++) {
            float4 p = *(const float4*)(Ks + j*64 + ((ty ^ (j & 15)) << 2));
            float4 v = *(const float4*)(Vs + j*64 + (tx << 2));
            o_[0][0] = fmaf(p.x, v.x, o_[0][0]); o_[0][1] = fmaf(p.x, v.y, o_[0][1]);
            o_[0][2] = fmaf(p.x, v.z, o_[0][2]); o_[0][3] = fmaf(p.x, v.w, o_[0][3]);
            o_[1][0] = fmaf(p.y, v.x, o_[1][0]); o_[1][1] = fmaf(p.y, v.y, o_[1][1]);
            o_[1][2] = fmaf(p.y, v.z, o_[1][2]); o_[1][3] = fmaf(p.y, v.w, o_[1][3]);
            o_[2][0] = fmaf(p.z, v.x, o_[2][0]); o_[2][1] = fmaf(p.z, v.y, o_[2][1]);
            o_[2][2] = fmaf(p.z, v.z, o_[2][2]); o_[2][3] = fmaf(p.z, v.w, o_[2][3]);
            o_[3][0] = fmaf(p.w, v.x, o_[3][0]); o_[3][1] = fmaf(p.w, v.y, o_[3][1]);
            o_[3][2] = fmaf(p.w, v.z, o_[3][2]); o_[3][3] = fmaf(p.w, v.w, o_[3][3]);
        }
    }

    const int b = bh / NH;
    const int h = bh - b * NH;
    #pragma unroll
    for (int ii = 0; ii < 4; ii++) {
        float inv = 1.f / l_[ii];
        int t = q0 + (ty<<2) + ii;
        float4 val;
        val.x = o_[ii][0] * inv;
        val.y = o_[ii][1] * inv;
        val.z = o_[ii][2] * inv;
        val.w = o_[ii][3] * inv;
        size_t idx = ((size_t)(b*SEQ + t))*D_MODEL + h*HEADD + (tx<<2);
        *(float4*)&g_o[idx] = val;
    }
}

// ============================================================
extern "C" void kernel_launch(void* const* d_in, const int* in_sizes, int n_in,
                              void* d_out, int out_size)
{
    const float* x  = (const float*)d_in[0];   // (B,T,768)
    const float* W1 = (const float*)d_in[1];   // (2304,768)
    const float* b1 = (const float*)d_in[2];
    const float* W2 = (const float*)d_in[3];   // (768,768)
    const float* b2 = (const float*)d_in[4];
    float* out = (float*)d_out;

    float* p_o;
    cudaGetSymbolAddress((void**)&p_o, g_o);
    __nv_bfloat16 *p_xh, *p_xl, *p_w1h, *p_w1l, *p_w2h, *p_w2l, *p_oh, *p_ol;
    cudaGetSymbolAddress((void**)&p_xh,  g_xh);
    cudaGetSymbolAddress((void**)&p_xl,  g_xl);
    cudaGetSymbolAddress((void**)&p_w1h, g_w1h);
    cudaGetSymbolAddress((void**)&p_w1l, g_w1l);
    cudaGetSymbolAddress((void**)&p_w2h, g_w2h);
    cudaGetSymbolAddress((void**)&p_w2l, g_w2l);
    cudaGetSymbolAddress((void**)&p_oh,  g_oh);
    cudaGetSymbolAddress((void**)&p_ol,  g_ol);

    cudaFuncSetAttribute(gemm_mma<0>, cudaFuncAttributeMaxDynamicSharedMemorySize, SMEM_GEMM);
    cudaFuncSetAttribute(gemm_mma<1>, cudaFuncAttributeMaxDynamicSharedMemorySize, SMEM_GEMM);

    // splits for x, W1, W2
    convert_split<<<(M_TOK*D_MODEL)/1024, 256>>>(x,  p_xh,  p_xl,  M_TOK*D_MODEL);
    convert_split<<<(N_QKV*D_MODEL)/1024, 256>>>(W1, p_w1h, p_w1l, N_QKV*D_MODEL);
    convert_split<<<(D_MODEL*D_MODEL)/1024, 256>>>(W2, p_w2h, p_w2l, D_MODEL*D_MODEL);

    // 1) QKV projection (mma.sync bf16x3), scatter to g_q/g_k/g_v
    gemm_mma<0><<<dim3(N_QKV/128, M_TOK/128), 256, SMEM_GEMM>>>(
        p_xh, p_xl, p_w1h, p_w1l, b1, nullptr, N_QKV);

    // 2) causal attention (SIMT fp32)
    attn_kernel<<<dim3(SEQ/64, BATCH*NH), 256>>>();

    // 3) output projection
    convert_split<<<(M_TOK*D_MODEL)/1024, 256>>>(p_o, p_oh, p_ol, M_TOK*D_MODEL);
    gemm_mma<1><<<dim3(D_MODEL/128, M_TOK/128), 256, SMEM_GEMM>>>(
        p_oh, p_ol, p_w2h, p_w2l, b2, out, D_MODEL);
}

// round 4
// speedup vs baseline: 3.3800x; 2.3601x over previous
#include <cuda_runtime.h>
#include <cuda_bf16.h>
#include <cstdint>

#define D_MODEL 768
#define NH      12
#define HEADD   64
#define BATCH   2
#define SEQ     2048
#define M_TOK   (BATCH*SEQ)   // 4096
#define N_QKV   (3*D_MODEL)   // 2304

// ============================================================
// helpers
// ============================================================
__device__ __forceinline__ uint32_t smem_u32(const void* p) {
    uint32_t a;
    asm("{ .reg .u64 t; cvta.to.shared.u64 t, %1; cvt.u32.u64 %0, t; }" : "=r"(a) : "l"(p));
    return a;
}

__device__ __forceinline__ void ldsm4(uint32_t* r, uint32_t addr) {
    asm volatile("ldmatrix.sync.aligned.m8n8.x4.shared.b16 {%0,%1,%2,%3}, [%4];"
        : "=r"(r[0]), "=r"(r[1]), "=r"(r[2]), "=r"(r[3]) : "r"(addr));
}
__device__ __forceinline__ void ldsm4t(uint32_t* r, uint32_t addr) {
    asm volatile("ldmatrix.sync.aligned.m8n8.x4.trans.shared.b16 {%0,%1,%2,%3}, [%4];"
        : "=r"(r[0]), "=r"(r[1]), "=r"(r[2]), "=r"(r[3]) : "r"(addr));
}

__device__ __forceinline__ void mma16816(float* c, const uint32_t* a, const uint32_t* b) {
    asm volatile(
        "mma.sync.aligned.m16n8k16.row.col.f32.bf16.bf16.f32 "
        "{%0,%1,%2,%3}, {%4,%5,%6,%7}, {%8,%9}, {%0,%1,%2,%3};"
        : "+f"(c[0]), "+f"(c[1]), "+f"(c[2]), "+f"(c[3])
        : "r"(a[0]), "r"(a[1]), "r"(a[2]), "r"(a[3]), "r"(b[0]), "r"(b[1]));
}

#define SWZ(off) ((off) ^ (((off) >> 3) & 0x70))

// split two fp32 into packed bf16 hi pair + lo pair
__device__ __forceinline__ void split2(float a, float b, uint32_t& hi, uint32_t& lo) {
    __nv_bfloat16 ha = __float2bfloat16(a), hb = __float2bfloat16(b);
    __nv_bfloat162 hh = __halves2bfloat162(ha, hb);
    hi = *(uint32_t*)&hh;
    __nv_bfloat162 ll = __halves2bfloat162(__float2bfloat16(a - __bfloat162float(ha)),
                                           __float2bfloat16(b - __bfloat162float(hb)));
    lo = *(uint32_t*)&ll;
}

// ---- scratch (device globals; no allocations allowed) ----
__device__ __align__(16) __nv_bfloat16 g_xh[(size_t)M_TOK*D_MODEL];
__device__ __align__(16) __nv_bfloat16 g_xl[(size_t)M_TOK*D_MODEL];
__device__ __align__(16) __nv_bfloat16 g_w1h[(size_t)N_QKV*D_MODEL];
__device__ __align__(16) __nv_bfloat16 g_w1l[(size_t)N_QKV*D_MODEL];
__device__ __align__(16) __nv_bfloat16 g_w2h[(size_t)D_MODEL*D_MODEL];
__device__ __align__(16) __nv_bfloat16 g_w2l[(size_t)D_MODEL*D_MODEL];
__device__ __align__(16) __nv_bfloat16 g_qh[(size_t)BATCH*NH*SEQ*HEADD];
__device__ __align__(16) __nv_bfloat16 g_ql[(size_t)BATCH*NH*SEQ*HEADD];
__device__ __align__(16) __nv_bfloat16 g_kh[(size_t)BATCH*NH*SEQ*HEADD];
__device__ __align__(16) __nv_bfloat16 g_kl[(size_t)BATCH*NH*SEQ*HEADD];
__device__ __align__(16) __nv_bfloat16 g_vh[(size_t)BATCH*NH*SEQ*HEADD];
__device__ __align__(16) __nv_bfloat16 g_vl[(size_t)BATCH*NH*SEQ*HEADD];
__device__ __align__(16) __nv_bfloat16 g_oh[(size_t)M_TOK*D_MODEL];
__device__ __align__(16) __nv_bfloat16 g_ol[(size_t)M_TOK*D_MODEL];

// ============================================================
// fp32 -> (bf16 hi, bf16 lo) split
// ============================================================
__global__ __launch_bounds__(256)
void convert_split(const float* __restrict__ src,
                   __nv_bfloat16* __restrict__ hi, __nv_bfloat16* __restrict__ lo, int n)
{
    int i = (blockIdx.x * blockDim.x + threadIdx.x) * 4;
    if (i >= n) return;
    float4 v = *(const float4*)(src + i);
    float f[4] = {v.x, v.y, v.z, v.w};
    __nv_bfloat16 h[4], l[4];
    #pragma unroll
    for (int j = 0; j < 4; j++) {
        h[j] = __float2bfloat16(f[j]);
        l[j] = __float2bfloat16(f[j] - __bfloat162float(h[j]));
    }
    *(__nv_bfloat162*)(hi + i)     = __halves2bfloat162(h[0], h[1]);
    *(__nv_bfloat162*)(hi + i + 2) = __halves2bfloat162(h[2], h[3]);
    *(__nv_bfloat162*)(lo + i)     = __halves2bfloat162(l[0], l[1]);
    *(__nv_bfloat162*)(lo + i + 2) = __halves2bfloat162(l[2], l[3]);
}

// ============================================================
// bf16x3 GEMM via mma.sync (128x128 CTA, 8 warps, 2-stage cp.async)
// MODE 0: +bias, split hi/lo, scatter to q/k/v (q pre-scaled by 1/8)
// MODE 1: +bias, store fp32 to C
// ============================================================
static constexpr int GBK     = 64;
static constexpr int NCH     = D_MODEL / GBK;    // 12
static constexpr int TILE_B  = 128 * 128;        // 16 KB
static constexpr int STAGE_B = 4 * TILE_B;       // 64 KB
static constexpr int SMEM_GEMM = 2 * STAGE_B;    // 128 KB

__device__ __forceinline__ void load_tile_async(uint32_t smem_tile, const __nv_bfloat16* g,
                                                int row0, int k0, int tid)
{
    #pragma unroll
    for (int i = 0; i < 4; i++) {
        int u  = tid + i * 256;
        int r  = u >> 3;
        int cu = u & 7;
        uint32_t dst = smem_tile + SWZ((uint32_t)(r * 128 + cu * 16));
        const void* src = g + (size_t)(row0 + r) * D_MODEL + k0 + cu * 8;
        asm volatile("cp.async.cg.shared.global [%0], [%1], 16;" :: "r"(dst), "l"(src) : "memory");
    }
}

template<int MODE>
__global__ __launch_bounds__(256, 1)
void gemm_mma(const __nv_bfloat16* __restrict__ Ah, const __nv_bfloat16* __restrict__ Al,
              const __nv_bfloat16* __restrict__ Bh, const __nv_bfloat16* __restrict__ Bl,
              const float* __restrict__ bias, float* __restrict__ C, int N)
{
    extern __shared__ __align__(1024) char smem[];
    const uint32_t sb = smem_u32(smem);
    const int tid  = threadIdx.x;
    const int wid  = tid >> 5;
    const int lane = tid & 31;
    const int wm   = wid & 1;
    const int wn   = wid >> 1;
    const int row0 = blockIdx.y * 128;
    const int col0 = blockIdx.x * 128;

    float acc[4][4][4] = {};

    const int aRow = wm * 64 + (lane & 15);
    const uint32_t xr = (uint32_t)((aRow & 7) << 4);
    const int aHalf = lane >> 4;
    const int bN = wn * 32 + (lane & 7) + ((lane >> 4) << 3);
    const uint32_t xn = (uint32_t)((lane & 7) << 4);
    const int bKb = ((lane >> 3) & 1) * 16;

    auto stage_addr = [&](int s) { return sb + (uint32_t)s * STAGE_B; };
    {
        uint32_t st = stage_addr(0);
        load_tile_async(st + 0*TILE_B, Ah, row0, 0, tid);
        load_tile_async(st + 1*TILE_B, Al, row0, 0, tid);
        load_tile_async(st + 2*TILE_B, Bh, col0, 0, tid);
        load_tile_async(st + 3*TILE_B, Bl, col0, 0, tid);
        asm volatile("cp.async.commit_group;" ::: "memory");
        st = stage_addr(1);
        load_tile_async(st + 0*TILE_B, Ah, row0, GBK, tid);
        load_tile_async(st + 1*TILE_B, Al, row0, GBK, tid);
        load_tile_async(st + 2*TILE_B, Bh, col0, GBK, tid);
        load_tile_async(st + 3*TILE_B, Bl, col0, GBK, tid);
        asm volatile("cp.async.commit_group;" ::: "memory");
    }

    for (int c = 0; c < NCH; c++) {
        const int s = c & 1;
        if (c < NCH - 1) asm volatile("cp.async.wait_group 1;" ::: "memory");
        else             asm volatile("cp.async.wait_group 0;" ::: "memory");
        __syncthreads();

        const uint32_t st   = stage_addr(s);
        const uint32_t stAh = st;
        const uint32_t stAl = st + TILE_B;
        const uint32_t stBh = st + 2*TILE_B;
        const uint32_t stBl = st + 3*TILE_B;

        #pragma unroll
        for (int ks = 0; ks < 4; ks++) {
            const uint32_t aKx = (uint32_t)((ks*32 + aHalf*16)) ^ xr;
            const uint32_t bKx = (uint32_t)((ks*32 + bKb)) ^ xn;

            uint32_t Afh[4][4], Afl[4][4], Bfh[2][4], Bfl[2][4];
            #pragma unroll
            for (int mi = 0; mi < 4; mi++) {
                uint32_t off = (uint32_t)((aRow + mi*16) * 128) + aKx;
                ldsm4(Afh[mi], stAh + off);
                ldsm4(Afl[mi], stAl + off);
            }
            #pragma unroll
            for (int j2 = 0; j2 < 2; j2++) {
                uint32_t off = (uint32_t)((bN + j2*16) * 128) + bKx;
                ldsm4(Bfh[j2], stBh + off);
                ldsm4(Bfl[j2], stBl + off);
            }
            #pragma unroll
            for (int mi = 0; mi < 4; mi++) {
                #pragma unroll
                for (int nj = 0; nj < 4; nj++) {
                    const uint32_t* bh = &Bfh[nj >> 1][(nj & 1) * 2];
                    const uint32_t* bl = &Bfl[nj >> 1][(nj & 1) * 2];
                    mma16816(acc[mi][nj], Afh[mi], bh);
                    mma16816(acc[mi][nj], Afh[mi], bl);
                    mma16816(acc[mi][nj], Afl[mi], bh);
                }
            }
        }
        __syncthreads();

        if (c + 2 < NCH) {
            uint32_t st2 = stage_addr(s);
            int k0 = (c + 2) * GBK;
            load_tile_async(st2 + 0*TILE_B, Ah, row0, k0, tid);
            load_tile_async(st2 + 1*TILE_B, Al, row0, k0, tid);
            load_tile_async(st2 + 2*TILE_B, Bh, col0, k0, tid);
            load_tile_async(st2 + 3*TILE_B, Bl, col0, k0, tid);
            asm volatile("cp.async.commit_group;" ::: "memory");
        }
    }

    #pragma unroll
    for (int mi = 0; mi < 4; mi++) {
        #pragma unroll
        for (int h2 = 0; h2 < 2; h2++) {
            const int m  = row0 + wm*64 + mi*16 + h2*8 + (lane >> 2);
            const int bb = m >> 11;
            const int t  = m & (SEQ - 1);
            #pragma unroll
            for (int nj = 0; nj < 4; nj++) {
                const int f = col0 + wn*32 + nj*8 + (lane & 3)*2;
                float vx = acc[mi][nj][h2*2+0] + bias[f];
                float vy = acc[mi][nj][h2*2+1] + bias[f+1];
                if (MODE == 0) {
                    int which = (f >= 1536) ? 2 : (f >= 768 ? 1 : 0);
                    int cc = f - which * 768;
                    int h = cc >> 6, d = cc & 63;
                    if (which == 0) { vx *= 0.125f; vy *= 0.125f; }
                    uint32_t hi, lo;
                    split2(vx, vy, hi, lo);
                    __nv_bfloat16* ph = (which == 0) ? g_qh : ((which == 1) ? g_kh : g_vh);
                    __nv_bfloat16* pl = (which == 0) ? g_ql : ((which == 1) ? g_kl : g_vl);
                    size_t idx = (((size_t)(bb*NH + h))*SEQ + t)*HEADD + d;
                    *(uint32_t*)&ph[idx] = hi;
                    *(uint32_t*)&pl[idx] = lo;
                } else {
                    float2 v; v.x = vx; v.y = vy;
                    *(float2*)&C[(size_t)m * N + f] = v;
                }
            }
        }
    }
}

// ============================================================
// Tensor-core flash attention (causal), bf16x3 split precision.
// Grid (16, 24): 128 queries per CTA per head. 8 warps (256 thr).
// kv chunks of 64, 2-stage cp.async pipeline.
// ============================================================
static constexpr int AQ_H  = 0;                 // Q hi: 128x128B = 16 KB
static constexpr int AQ_L  = 16384;             // Q lo
static constexpr int AST0  = 32768;             // stage 0: Kh,Kl,Vh,Vl (4 x 8 KB)
static constexpr int ASTG  = 32768;             // stage stride
static constexpr int SMEM_ATTN = 32768 + 2*ASTG;  // 96 KB

__device__ __forceinline__ void load_kv_async(uint32_t st, const __nv_bfloat16* Kh,
    const __nv_bfloat16* Kl, const __nv_bfloat16* Vh, const __nv_bfloat16* Vl,
    int kc, int tid)
{
    #pragma unroll
    for (int i = 0; i < 2; i++) {
        int u  = tid + i * 256;      // 0..511
        int r  = u >> 3;             // 0..63
        int cu = u & 7;
        uint32_t dsw = SWZ((uint32_t)(r * 128 + cu * 16));
        size_t src = (size_t)(kc + r) * HEADD + cu * 8;
        asm volatile("cp.async.cg.shared.global [%0], [%1], 16;" :: "r"(st + dsw),          "l"((const void*)(Kh + src)) : "memory");
        asm volatile("cp.async.cg.shared.global [%0], [%1], 16;" :: "r"(st + 8192 + dsw),   "l"((const void*)(Kl + src)) : "memory");
        asm volatile("cp.async.cg.shared.global [%0], [%1], 16;" :: "r"(st + 16384 + dsw),  "l"((const void*)(Vh + src)) : "memory");
        asm volatile("cp.async.cg.shared.global [%0], [%1], 16;" :: "r"(st + 24576 + dsw),  "l"((const void*)(Vl + src)) : "memory");
    }
}

__global__ __launch_bounds__(256, 1)
void attn_mma()
{
    extern __shared__ __align__(1024) char smem[];
    const uint32_t sb = smem_u32(smem);
    const int tid  = threadIdx.x;
    const int wid  = tid >> 5;
    const int lane = tid & 31;
    const int bh   = blockIdx.y;
    const int qt   = gridDim.x - 1 - blockIdx.x;   // heavy CTAs first
    const int q0   = qt * 128;
    const int m0   = wid * 16;
    const int nch  = 2 * qt + 2;

    const size_t hoff = (size_t)bh * SEQ * HEADD;
    const __nv_bfloat16* Qh = g_qh + hoff;
    const __nv_bfloat16* Ql = g_ql + hoff;
    const __nv_bfloat16* Kh = g_kh + hoff;
    const __nv_bfloat16* Kl = g_kl + hoff;
    const __nv_bfloat16* Vh = g_vh + hoff;
    const __nv_bfloat16* Vl = g_vl + hoff;

    // prologue: Q + chunk0 (group A), chunk1 (group B)
    #pragma unroll
    for (int i = 0; i < 4; i++) {
        int u  = tid + i * 256;      // 0..1023
        int r  = u >> 3;             // 0..127
        int cu = u & 7;
        uint32_t dsw = SWZ((uint32_t)(r * 128 + cu * 16));
        size_t src = (size_t)(q0 + r) * HEADD + cu * 8;
        asm volatile("cp.async.cg.shared.global [%0], [%1], 16;" :: "r"(sb + AQ_H + dsw), "l"((const void*)(Qh + src)) : "memory");
        asm volatile("cp.async.cg.shared.global [%0], [%1], 16;" :: "r"(sb + AQ_L + dsw), "l"((const void*)(Ql + src)) : "memory");
    }
    load_kv_async(sb + AST0, Kh, Kl, Vh, Vl, 0, tid);
    asm volatile("cp.async.commit_group;" ::: "memory");
    load_kv_async(sb + AST0 + ASTG, Kh, Kl, Vh, Vl, 64, tid);
    asm volatile("cp.async.commit_group;" ::: "memory");

    uint32_t QfH[4][4], QfL[4][4];
    float o[8][4] = {};
    float m_[2] = {-1e30f, -1e30f};
    float l_[2] = {0.f, 0.f};

    // ldmatrix geometry
    const uint32_t aoff0 = (uint32_t)((m0 + (lane & 15)) * 128) ;
    const int aHalf = (lane >> 4) * 16;
    const int krow = (lane & 7) + ((lane >> 4) << 3);
    const int kcb  = ((lane >> 3) & 1) * 16;
    const int vg   = lane >> 3;
    const int vr   = lane & 7;

    for (int c = 0; c < nch; c++) {
        const int s = c & 1;
        if (c < nch - 1) asm volatile("cp.async.wait_group 1;" ::: "memory");
        else             asm volatile("cp.async.wait_group 0;" ::: "memory");
        __syncthreads();

        if (c == 0) {
            #pragma unroll
            for (int kc = 0; kc < 4; kc++) {
                uint32_t off = SWZ(aoff0 + (uint32_t)(kc*32 + aHalf));
                ldsm4(QfH[kc], sb + AQ_H + off);
                ldsm4(QfL[kc], sb + AQ_L + off);
            }
        }

        const uint32_t stK = sb + AST0 + (uint32_t)s * ASTG;
        const uint32_t stKl = stK + 8192;
        const uint32_t stV  = stK + 16384;
        const uint32_t stVl = stK + 24576;

        // ---- S = Q K^T ----
        float sc[8][4] = {};
        #pragma unroll
        for (int kc = 0; kc < 4; kc++) {
            #pragma unroll
            for (int np = 0; np < 4; np++) {
                uint32_t off = SWZ((uint32_t)((np*16 + krow) * 128 + kc*32 + kcb));
                uint32_t Bh_[4], Bl_[4];
                ldsm4(Bh_, stK  + off);
                ldsm4(Bl_, stKl + off);
                mma16816(sc[2*np],   QfH[kc], &Bh_[0]);
                mma16816(sc[2*np],   QfH[kc], &Bl_[0]);
                mma16816(sc[2*np],   QfL[kc], &Bh_[0]);
                mma16816(sc[2*np+1], QfH[kc], &Bh_[2]);
                mma16816(sc[2*np+1], QfH[kc], &Bl_[2]);
                mma16816(sc[2*np+1], QfL[kc], &Bh_[2]);
            }
        }

        // ---- causal mask (last two chunks only) ----
        if (c >= nch - 2) {
            const int qr0 = q0 + m0 + (lane >> 2);
            const int cb  = c*64 + (lane & 3)*2;
            #pragma unroll
            for (int nj = 0; nj < 8; nj++) {
                int col = cb + nj*8;
                if (col     > qr0)     sc[nj][0] = -1e30f;
                if (col + 1 > qr0)     sc[nj][1] = -1e30f;
                if (col     > qr0 + 8) sc[nj][2] = -1e30f;
                if (col + 1 > qr0 + 8) sc[nj][3] = -1e30f;
            }
        }

        // ---- online softmax (two rows per thread) ----
        #pragma unroll
        for (int rr = 0; rr < 2; rr++) {
            float mx = -1e30f;
            #pragma unroll
            for (int nj = 0; nj < 8; nj++)
                mx = fmaxf(mx, fmaxf(sc[nj][2*rr], sc[nj][2*rr+1]));
            mx = fmaxf(mx, __shfl_xor_sync(0xffffffffu, mx, 1));
            mx = fmaxf(mx, __shfl_xor_sync(0xffffffffu, mx, 2));
            float mn   = fmaxf(m_[rr], mx);
            float corr = __expf(m_[rr] - mn);
            float rs = 0.f;
            #pragma unroll
            for (int nj = 0; nj < 8; nj++) {
                float p0 = __expf(sc[nj][2*rr]   - mn);
                float p1 = __expf(sc[nj][2*rr+1] - mn);
                sc[nj][2*rr]   = p0;
                sc[nj][2*rr+1] = p1;
                rs += p0 + p1;
            }
            rs += __shfl_xor_sync(0xffffffffu, rs, 1);
            rs += __shfl_xor_sync(0xffffffffu, rs, 2);
            l_[rr] = l_[rr] * corr + rs;
            m_[rr] = mn;
            #pragma unroll
            for (int nj = 0; nj < 8; nj++) {
                o[nj][2*rr]   *= corr;
                o[nj][2*rr+1] *= corr;
            }
        }

        // ---- P -> bf16 hi/lo A-fragments (in registers) ----
        uint32_t AH[4][4], AL[4][4];
        #pragma unroll
        for (int c2 = 0; c2 < 4; c2++) {
            split2(sc[2*c2][0],   sc[2*c2][1],   AH[c2][0], AL[c2][0]);
            split2(sc[2*c2][2],   sc[2*c2][3],   AH[c2][1], AL[c2][1]);
            split2(sc[2*c2+1][0], sc[2*c2+1][1], AH[c2][2], AL[c2][2]);
            split2(sc[2*c2+1][2], sc[2*c2+1][3], AH[c2][3], AL[c2][3]);
        }

        // ---- O += P V ----
        #pragma unroll
        for (int jc = 0; jc < 4; jc++) {
            #pragma unroll
            for (int dp = 0; dp < 4; dp++) {
                uint32_t off = SWZ((uint32_t)((jc*16 + (vg & 1)*8 + vr) * 128 + (dp*16 + (vg >> 1)*8) * 2));
                uint32_t Vh_[4], Vl_[4];
                ldsm4t(Vh_, stV  + off);
                ldsm4t(Vl_, stVl + off);
                mma16816(o[2*dp],   AH[jc], &Vh_[0]);
                mma16816(o[2*dp],   AH[jc], &Vl_[0]);
                mma16816(o[2*dp],   AL[jc], &Vh_[0]);
                mma16816(o[2*dp+1], AH[jc], &Vh_[2]);
                mma16816(o[2*dp+1], AH[jc], &Vl_[2]);
                mma16816(o[2*dp+1], AL[jc], &Vh_[2]);
            }
        }

        __syncthreads();
        if (c + 2 < nch) {
            load_kv_async(sb + AST0 + (uint32_t)s * ASTG, Kh, Kl, Vh, Vl, (c + 2) * 64, tid);
            asm volatile("cp.async.commit_group;" ::: "memory");
        }
    }

    // ---- epilogue: O/l -> bf16 hi/lo in (token, 768) layout ----
    const int b = bh / NH;
    const int h = bh - b * NH;
    const float inv0 = 1.f / l_[0];
    const float inv1 = 1.f / l_[1];
    const int q = q0 + m0 + (lane >> 2);
    const size_t tok0 = (size_t)(b * SEQ + q) * D_MODEL;
    const size_t tok1 = tok0 + 8 * D_MODEL;
    #pragma unroll
    for (int nj = 0; nj < 8; nj++) {
        const int dc = h * HEADD + nj*8 + (lane & 3)*2;
        uint32_t hi, lo;
        split2(o[nj][0] * inv0, o[nj][1] * inv0, hi, lo);
        *(uint32_t*)&g_oh[tok0 + dc] = hi;
        *(uint32_t*)&g_ol[tok0 + dc] = lo;
        split2(o[nj][2] * inv1, o[nj][3] * inv1, hi, lo);
        *(uint32_t*)&g_oh[tok1 + dc] = hi;
        *(uint32_t*)&g_ol[tok1 + dc] = lo;
    }
}

// ============================================================
extern "C" void kernel_launch(void* const* d_in, const int* in_sizes, int n_in,
                              void* d_out, int out_size)
{
    const float* x  = (const float*)d_in[0];   // (B,T,768)
    const float* W1 = (const float*)d_in[1];   // (2304,768)
    const float* b1 = (const float*)d_in[2];
    const float* W2 = (const float*)d_in[3];   // (768,768)
    const float* b2 = (const float*)d_in[4];
    float* out = (float*)d_out;

    __nv_bfloat16 *p_xh, *p_xl, *p_w1h, *p_w1l, *p_w2h, *p_w2l, *p_oh, *p_ol;
    cudaGetSymbolAddress((void**)&p_xh,  g_xh);
    cudaGetSymbolAddress((void**)&p_xl,  g_xl);
    cudaGetSymbolAddress((void**)&p_w1h, g_w1h);
    cudaGetSymbolAddress((void**)&p_w1l, g_w1l);
    cudaGetSymbolAddress((void**)&p_w2h, g_w2h);
    cudaGetSymbolAddress((void**)&p_w2l, g_w2l);
    cudaGetSymbolAddress((void**)&p_oh,  g_oh);
    cudaGetSymbolAddress((void**)&p_ol,  g_ol);

    cudaFuncSetAttribute(gemm_mma<0>, cudaFuncAttributeMaxDynamicSharedMemorySize, SMEM_GEMM);
    cudaFuncSetAttribute(gemm_mma<1>, cudaFuncAttributeMaxDynamicSharedMemorySize, SMEM_GEMM);
    cudaFuncSetAttribute(attn_mma,    cudaFuncAttributeMaxDynamicSharedMemorySize, SMEM_ATTN);

    convert_split<<<(M_TOK*D_MODEL)/1024, 256>>>(x,  p_xh,  p_xl,  M_TOK*D_MODEL);
    convert_split<<<(N_QKV*D_MODEL)/1024, 256>>>(W1, p_w1h, p_w1l, N_QKV*D_MODEL);
    convert_split<<<(D_MODEL*D_MODEL)/1024, 256>>>(W2, p_w2h, p_w2l, D_MODEL*D_MODEL);

    // 1) QKV projection -> bf16 hi/lo q/k/v (q scaled by 1/8)
    gemm_mma<0><<<dim3(N_QKV/128, M_TOK/128), 256, SMEM_GEMM>>>(
        p_xh, p_xl, p_w1h, p_w1l, b1, nullptr, N_QKV);

    // 2) tensor-core causal flash attention -> bf16 hi/lo O
    attn_mma<<<dim3(SEQ/128, BATCH*NH), 256, SMEM_ATTN>>>();

    // 3) output projection
    gemm_mma<1><<<dim3(D_MODEL/128, M_TOK/128), 256, SMEM_GEMM>>>(
        p_oh, p_ol, p_w2h, p_w2l, b2, out, D_MODEL);
}

// round 5
// speedup vs baseline: 3.9299x; 1.1627x over previous
#include <cuda_runtime.h>
#include <cuda_bf16.h>
#include <cuda_fp16.h>
#include <cstdint>

#define D_MODEL 768
#define NH      12
#define HEADD   64
#define BATCH   2
#define SEQ     2048
#define M_TOK   (BATCH*SEQ)   // 4096
#define N_QKV   (3*D_MODEL)   // 2304

// ============================================================
// helpers
// ============================================================
__device__ __forceinline__ uint32_t smem_u32(const void* p) {
    uint32_t a;
    asm("{ .reg .u64 t; cvta.to.shared.u64 t, %1; cvt.u32.u64 %0, t; }" : "=r"(a) : "l"(p));
    return a;
}

__device__ __forceinline__ void ldsm4(uint32_t* r, uint32_t addr) {
    asm volatile("ldmatrix.sync.aligned.m8n8.x4.shared.b16 {%0,%1,%2,%3}, [%4];"
        : "=r"(r[0]), "=r"(r[1]), "=r"(r[2]), "=r"(r[3]) : "r"(addr));
}
__device__ __forceinline__ void ldsm4t(uint32_t* r, uint32_t addr) {
    asm volatile("ldmatrix.sync.aligned.m8n8.x4.trans.shared.b16 {%0,%1,%2,%3}, [%4];"
        : "=r"(r[0]), "=r"(r[1]), "=r"(r[2]), "=r"(r[3]) : "r"(addr));
}

__device__ __forceinline__ void mma16816(float* c, const uint32_t* a, const uint32_t* b) {
    asm volatile(
        "mma.sync.aligned.m16n8k16.row.col.f32.bf16.bf16.f32 "
        "{%0,%1,%2,%3}, {%4,%5,%6,%7}, {%8,%9}, {%0,%1,%2,%3};"
        : "+f"(c[0]), "+f"(c[1]), "+f"(c[2]), "+f"(c[3])
        : "r"(a[0]), "r"(a[1]), "r"(a[2]), "r"(a[3]), "r"(b[0]), "r"(b[1]));
}
__device__ __forceinline__ void mma16816h(float* c, const uint32_t* a, const uint32_t* b) {
    asm volatile(
        "mma.sync.aligned.m16n8k16.row.col.f32.f16.f16.f32 "
        "{%0,%1,%2,%3}, {%4,%5,%6,%7}, {%8,%9}, {%0,%1,%2,%3};"
        : "+f"(c[0]), "+f"(c[1]), "+f"(c[2]), "+f"(c[3])
        : "r"(a[0]), "r"(a[1]), "r"(a[2]), "r"(a[3]), "r"(b[0]), "r"(b[1]));
}

#define SWZ(off) ((off) ^ (((off) >> 3) & 0x70))

// split two fp32 into packed bf16 hi pair + lo pair
__device__ __forceinline__ void split2(float a, float b, uint32_t& hi, uint32_t& lo) {
    __nv_bfloat16 ha = __float2bfloat16(a), hb = __float2bfloat16(b);
    __nv_bfloat162 hh = __halves2bfloat162(ha, hb);
    hi = *(uint32_t*)&hh;
    __nv_bfloat162 ll = __halves2bfloat162(__float2bfloat16(a - __bfloat162float(ha)),
                                           __float2bfloat16(b - __bfloat162float(hb)));
    lo = *(uint32_t*)&ll;
}
// split two fp32 into packed fp16 hi pair + lo pair
__device__ __forceinline__ void split2h(float a, float b, uint32_t& hi, uint32_t& lo) {
    __half2 h2 = __floats2half2_rn(a, b);
    hi = *(uint32_t*)&h2;
    float2 hf = __half22float2(h2);
    __half2 l2 = __floats2half2_rn(a - hf.x, b - hf.y);
    lo = *(uint32_t*)&l2;
}

// ---- scratch (device globals; no allocations allowed) ----
__device__ __align__(16) __nv_bfloat16 g_xh[(size_t)M_TOK*D_MODEL];
__device__ __align__(16) __nv_bfloat16 g_xl[(size_t)M_TOK*D_MODEL];
__device__ __align__(16) __nv_bfloat16 g_w1h[(size_t)N_QKV*D_MODEL];
__device__ __align__(16) __nv_bfloat16 g_w1l[(size_t)N_QKV*D_MODEL];
__device__ __align__(16) __nv_bfloat16 g_w2h[(size_t)D_MODEL*D_MODEL];
__device__ __align__(16) __nv_bfloat16 g_w2l[(size_t)D_MODEL*D_MODEL];
__device__ __align__(16) __half g_qh[(size_t)BATCH*NH*SEQ*HEADD];
__device__ __align__(16) __half g_ql[(size_t)BATCH*NH*SEQ*HEADD];
__device__ __align__(16) __half g_kh[(size_t)BATCH*NH*SEQ*HEADD];
__device__ __align__(16) __half g_vh[(size_t)BATCH*NH*SEQ*HEADD];
__device__ __align__(16) __nv_bfloat16 g_oh[(size_t)M_TOK*D_MODEL];
__device__ __align__(16) __nv_bfloat16 g_ol[(size_t)M_TOK*D_MODEL];

// ============================================================
// fp32 -> (bf16 hi, bf16 lo) split
// ============================================================
__global__ __launch_bounds__(256)
void convert_split(const float* __restrict__ src,
                   __nv_bfloat16* __restrict__ hi, __nv_bfloat16* __restrict__ lo, int n)
{
    int i = (blockIdx.x * blockDim.x + threadIdx.x) * 4;
    if (i >= n) return;
    float4 v = *(const float4*)(src + i);
    float f[4] = {v.x, v.y, v.z, v.w};
    __nv_bfloat16 h[4], l[4];
    #pragma unroll
    for (int j = 0; j < 4; j++) {
        h[j] = __float2bfloat16(f[j]);
        l[j] = __float2bfloat16(f[j] - __bfloat162float(h[j]));
    }
    *(__nv_bfloat162*)(hi + i)     = __halves2bfloat162(h[0], h[1]);
    *(__nv_bfloat162*)(hi + i + 2) = __halves2bfloat162(h[2], h[3]);
    *(__nv_bfloat162*)(lo + i)     = __halves2bfloat162(l[0], l[1]);
    *(__nv_bfloat162*)(lo + i + 2) = __halves2bfloat162(l[2], l[3]);
}

// ============================================================
// bf16x3 GEMM via mma.sync (128x128 CTA, 8 warps, 2-stage cp.async)
// MODE 0: +bias, emit fp16: q hi/lo (scaled 1/8), k hi, v hi
// MODE 1: +bias, store fp32 to C
// ============================================================
static constexpr int GBK     = 64;
static constexpr int NCH     = D_MODEL / GBK;    // 12
static constexpr int TILE_B  = 128 * 128;        // 16 KB
static constexpr int STAGE_B = 4 * TILE_B;       // 64 KB
static constexpr int SMEM_GEMM = 2 * STAGE_B;    // 128 KB

__device__ __forceinline__ void load_tile_async(uint32_t smem_tile, const __nv_bfloat16* g,
                                                int row0, int k0, int tid)
{
    #pragma unroll
    for (int i = 0; i < 4; i++) {
        int u  = tid + i * 256;
        int r  = u >> 3;
        int cu = u & 7;
        uint32_t dst = smem_tile + SWZ((uint32_t)(r * 128 + cu * 16));
        const void* src = g + (size_t)(row0 + r) * D_MODEL + k0 + cu * 8;
        asm volatile("cp.async.cg.shared.global [%0], [%1], 16;" :: "r"(dst), "l"(src) : "memory");
    }
}

template<int MODE>
__global__ __launch_bounds__(256, 1)
void gemm_mma(const __nv_bfloat16* __restrict__ Ah, const __nv_bfloat16* __restrict__ Al,
              const __nv_bfloat16* __restrict__ Bh, const __nv_bfloat16* __restrict__ Bl,
              const float* __restrict__ bias, float* __restrict__ C, int N)
{
    extern __shared__ __align__(1024) char smem[];
    const uint32_t sb = smem_u32(smem);
    const int tid  = threadIdx.x;
    const int wid  = tid >> 5;
    const int lane = tid & 31;
    const int wm   = wid & 1;
    const int wn   = wid >> 1;
    const int row0 = blockIdx.y * 128;
    const int col0 = blockIdx.x * 128;

    float acc[4][4][4] = {};

    const int aRow = wm * 64 + (lane & 15);
    const uint32_t xr = (uint32_t)((aRow & 7) << 4);
    const int aHalf = lane >> 4;
    const int bN = wn * 32 + (lane & 7) + ((lane >> 4) << 3);
    const uint32_t xn = (uint32_t)((lane & 7) << 4);
    const int bKb = ((lane >> 3) & 1) * 16;

    auto stage_addr = [&](int s) { return sb + (uint32_t)s * STAGE_B; };
    {
        uint32_t st = stage_addr(0);
        load_tile_async(st + 0*TILE_B, Ah, row0, 0, tid);
        load_tile_async(st + 1*TILE_B, Al, row0, 0, tid);
        load_tile_async(st + 2*TILE_B, Bh, col0, 0, tid);
        load_tile_async(st + 3*TILE_B, Bl, col0, 0, tid);
        asm volatile("cp.async.commit_group;" ::: "memory");
        st = stage_addr(1);
        load_tile_async(st + 0*TILE_B, Ah, row0, GBK, tid);
        load_tile_async(st + 1*TILE_B, Al, row0, GBK, tid);
        load_tile_async(st + 2*TILE_B, Bh, col0, GBK, tid);
        load_tile_async(st + 3*TILE_B, Bl, col0, GBK, tid);
        asm volatile("cp.async.commit_group;" ::: "memory");
    }

    for (int c = 0; c < NCH; c++) {
        const int s = c & 1;
        if (c < NCH - 1) asm volatile("cp.async.wait_group 1;" ::: "memory");
        else             asm volatile("cp.async.wait_group 0;" ::: "memory");
        __syncthreads();

        const uint32_t st   = stage_addr(s);
        const uint32_t stAh = st;
        const uint32_t stAl = st + TILE_B;
        const uint32_t stBh = st + 2*TILE_B;
        const uint32_t stBl = st + 3*TILE_B;

        #pragma unroll
        for (int ks = 0; ks < 4; ks++) {
            const uint32_t aKx = (uint32_t)((ks*32 + aHalf*16)) ^ xr;
            const uint32_t bKx = (uint32_t)((ks*32 + bKb)) ^ xn;

            uint32_t Afh[4][4], Afl[4][4], Bfh[2][4], Bfl[2][4];
            #pragma unroll
            for (int mi = 0; mi < 4; mi++) {
                uint32_t off = (uint32_t)((aRow + mi*16) * 128) + aKx;
                ldsm4(Afh[mi], stAh + off);
                ldsm4(Afl[mi], stAl + off);
            }
            #pragma unroll
            for (int j2 = 0; j2 < 2; j2++) {
                uint32_t off = (uint32_t)((bN + j2*16) * 128) + bKx;
                ldsm4(Bfh[j2], stBh + off);
                ldsm4(Bfl[j2], stBl + off);
            }
            #pragma unroll
            for (int mi = 0; mi < 4; mi++) {
                #pragma unroll
                for (int nj = 0; nj < 4; nj++) {
                    const uint32_t* bh = &Bfh[nj >> 1][(nj & 1) * 2];
                    const uint32_t* bl = &Bfl[nj >> 1][(nj & 1) * 2];
                    mma16816(acc[mi][nj], Afh[mi], bh);
                    mma16816(acc[mi][nj], Afh[mi], bl);
                    mma16816(acc[mi][nj], Afl[mi], bh);
                }
            }
        }
        __syncthreads();

        if (c + 2 < NCH) {
            uint32_t st2 = stage_addr(s);
            int k0 = (c + 2) * GBK;
            load_tile_async(st2 + 0*TILE_B, Ah, row0, k0, tid);
            load_tile_async(st2 + 1*TILE_B, Al, row0, k0, tid);
            load_tile_async(st2 + 2*TILE_B, Bh, col0, k0, tid);
            load_tile_async(st2 + 3*TILE_B, Bl, col0, k0, tid);
            asm volatile("cp.async.commit_group;" ::: "memory");
        }
    }

    #pragma unroll
    for (int mi = 0; mi < 4; mi++) {
        #pragma unroll
        for (int h2 = 0; h2 < 2; h2++) {
            const int m  = row0 + wm*64 + mi*16 + h2*8 + (lane >> 2);
            const int bb = m >> 11;
            const int t  = m & (SEQ - 1);
            #pragma unroll
            for (int nj = 0; nj < 4; nj++) {
                const int f = col0 + wn*32 + nj*8 + (lane & 3)*2;
                float vx = acc[mi][nj][h2*2+0] + bias[f];
                float vy = acc[mi][nj][h2*2+1] + bias[f+1];
                if (MODE == 0) {
                    int which = (f >= 1536) ? 2 : (f >= 768 ? 1 : 0);
                    int cc = f - which * 768;
                    int h = cc >> 6, d = cc & 63;
                    size_t idx = (((size_t)(bb*NH + h))*SEQ + t)*HEADD + d;
                    if (which == 0) {
                        uint32_t hi, lo;
                        split2h(vx * 0.125f, vy * 0.125f, hi, lo);
                        *(uint32_t*)&g_qh[idx] = hi;
                        *(uint32_t*)&g_ql[idx] = lo;
                    } else {
                        __half2 hv = __floats2half2_rn(vx, vy);
                        __half* dst = (which == 1) ? g_kh : g_vh;
                        *(uint32_t*)&dst[idx] = *(uint32_t*)&hv;
                    }
                } else {
                    float2 v; v.x = vx; v.y = vy;
                    *(float2*)&C[(size_t)m * N + f] = v;
                }
            }
        }
    }
}

// ============================================================
// Tensor-core flash attention (causal), fp16 2-pass.
// Grid (16, 24): 128 queries per CTA per head, 8 warps.
// kv chunks of 128 rows, 2-stage cp.async pipeline.
// S = (qh+ql)*kh  (2 mma passes, shared K frag)
// O = (Ph+Pl)*vh  (2 mma passes, shared V frag)
// ============================================================
static constexpr int AQ_H  = 0;                  // Q hi: 128x128B = 16 KB
static constexpr int AQ_L  = 16384;              // Q lo
static constexpr int AST0  = 32768;              // stages: Kh(16KB), Vh(16KB)
static constexpr int ASTG  = 32768;
static constexpr int SMEM_ATTN = 32768 + 2*ASTG; // 96 KB

__device__ __forceinline__ void load_kv_async(uint32_t st, const __half* Kh,
                                              const __half* Vh, int kc, int tid)
{
    #pragma unroll
    for (int i = 0; i < 4; i++) {
        int u  = tid + i * 256;      // 0..1023
        int r  = u >> 3;             // 0..127
        int cu = u & 7;
        uint32_t dsw = SWZ((uint32_t)(r * 128 + cu * 16));
        size_t src = (size_t)(kc + r) * HEADD + cu * 8;
        asm volatile("cp.async.cg.shared.global [%0], [%1], 16;" :: "r"(st + dsw),         "l"((const void*)(Kh + src)) : "memory");
        asm volatile("cp.async.cg.shared.global [%0], [%1], 16;" :: "r"(st + 16384 + dsw), "l"((const void*)(Vh + src)) : "memory");
    }
}

__global__ __launch_bounds__(256, 1)
void attn_mma()
{
    extern __shared__ __align__(1024) char smem[];
    const uint32_t sb = smem_u32(smem);
    const int tid  = threadIdx.x;
    const int wid  = tid >> 5;
    const int lane = tid & 31;
    const int bh   = blockIdx.y;
    const int qt   = gridDim.x - 1 - blockIdx.x;   // heavy CTAs first
    const int q0   = qt * 128;
    const int m0   = wid * 16;
    const int nch  = qt + 1;

    const size_t hoff = (size_t)bh * SEQ * HEADD;
    const __half* Qh = g_qh + hoff;
    const __half* Ql = g_ql + hoff;
    const __half* Kh = g_kh + hoff;
    const __half* Vh = g_vh + hoff;

    // prologue: Q tiles + chunk0/chunk1 KV
    #pragma unroll
    for (int i = 0; i < 4; i++) {
        int u  = tid + i * 256;
        int r  = u >> 3;
        int cu = u & 7;
        uint32_t dsw = SWZ((uint32_t)(r * 128 + cu * 16));
        size_t src = (size_t)(q0 + r) * HEADD + cu * 8;
        asm volatile("cp.async.cg.shared.global [%0], [%1], 16;" :: "r"(sb + AQ_H + dsw), "l"((const void*)(Qh + src)) : "memory");
        asm volatile("cp.async.cg.shared.global [%0], [%1], 16;" :: "r"(sb + AQ_L + dsw), "l"((const void*)(Ql + src)) : "memory");
    }
    load_kv_async(sb + AST0, Kh, Vh, 0, tid);
    asm volatile("cp.async.commit_group;" ::: "memory");
    load_kv_async(sb + AST0 + ASTG, Kh, Vh, 128, tid);
    asm volatile("cp.async.commit_group;" ::: "memory");

    uint32_t QfH[4][4], QfL[4][4];
    float o[8][4] = {};
    float m_[2] = {-1e30f, -1e30f};
    float l_[2] = {0.f, 0.f};

    // ldmatrix geometry
    const uint32_t aoff0 = (uint32_t)((m0 + (lane & 15)) * 128);
    const int aHalf = (lane >> 4) * 16;
    const int krow = (lane & 7) + ((lane >> 4) << 3);
    const int kcb  = ((lane >> 3) & 1) * 16;
    const int vg   = lane >> 3;
    const int vr   = lane & 7;

    for (int c = 0; c < nch; c++) {
        const int s = c & 1;
        if (c < nch - 1) asm volatile("cp.async.wait_group 1;" ::: "memory");
        else             asm volatile("cp.async.wait_group 0;" ::: "memory");
        __syncthreads();

        if (c == 0) {
            #pragma unroll
            for (int kc = 0; kc < 4; kc++) {
                uint32_t off = SWZ(aoff0 + (uint32_t)(kc*32 + aHalf));
                ldsm4(QfH[kc], sb + AQ_H + off);
                ldsm4(QfL[kc], sb + AQ_L + off);
            }
        }

        const uint32_t stK = sb + AST0 + (uint32_t)s * ASTG;
        const uint32_t stV = stK + 16384;

        // ---- S = (Qh+Ql) K^T : 2 passes, shared K frag ----
        float sc[16][4];
        #pragma unroll
        for (int nj = 0; nj < 16; nj++) { sc[nj][0]=0.f; sc[nj][1]=0.f; sc[nj][2]=0.f; sc[nj][3]=0.f; }
        #pragma unroll
        for (int kc = 0; kc < 4; kc++) {
            #pragma unroll
            for (int np = 0; np < 8; np++) {
                uint32_t off = SWZ((uint32_t)((np*16 + krow) * 128 + kc*32 + kcb));
                uint32_t Bf[4];
                ldsm4(Bf, stK + off);
                mma16816h(sc[2*np],   QfH[kc], &Bf[0]);
                mma16816h(sc[2*np],   QfL[kc], &Bf[0]);
                mma16816h(sc[2*np+1], QfH[kc], &Bf[2]);
                mma16816h(sc[2*np+1], QfL[kc], &Bf[2]);
            }
        }

        // ---- causal mask (diagonal chunk only) ----
        if (c == nch - 1) {
            const int qr0 = q0 + m0 + (lane >> 2);
            const int cb  = c*128 + (lane & 3)*2;
            #pragma unroll
            for (int nj = 0; nj < 16; nj++) {
                int col = cb + nj*8;
                if (col     > qr0)     sc[nj][0] = -1e30f;
                if (col + 1 > qr0)     sc[nj][1] = -1e30f;
                if (col     > qr0 + 8) sc[nj][2] = -1e30f;
                if (col + 1 > qr0 + 8) sc[nj][3] = -1e30f;
            }
        }

        // ---- online softmax (two rows per thread) ----
        #pragma unroll
        for (int rr = 0; rr < 2; rr++) {
            float mx = -1e30f;
            #pragma unroll
            for (int nj = 0; nj < 16; nj++)
                mx = fmaxf(mx, fmaxf(sc[nj][2*rr], sc[nj][2*rr+1]));
            mx = fmaxf(mx, __shfl_xor_sync(0xffffffffu, mx, 1));
            mx = fmaxf(mx, __shfl_xor_sync(0xffffffffu, mx, 2));
            float mn   = fmaxf(m_[rr], mx);
            float corr = __expf(m_[rr] - mn);
            float rs = 0.f;
            #pragma unroll
            for (int nj = 0; nj < 16; nj++) {
                float p0 = __expf(sc[nj][2*rr]   - mn);
                float p1 = __expf(sc[nj][2*rr+1] - mn);
                sc[nj][2*rr]   = p0;
                sc[nj][2*rr+1] = p1;
                rs += p0 + p1;
            }
            rs += __shfl_xor_sync(0xffffffffu, rs, 1);
            rs += __shfl_xor_sync(0xffffffffu, rs, 2);
            l_[rr] = l_[rr] * corr + rs;
            m_[rr] = mn;
            #pragma unroll
            for (int nj = 0; nj < 8; nj++) {
                o[nj][2*rr]   *= corr;
                o[nj][2*rr+1] *= corr;
            }
        }

        // ---- O += (Ph+Pl) V : 2 passes, shared V frag ----
        #pragma unroll
        for (int jc = 0; jc < 8; jc++) {
            uint32_t AH[4], AL[4];
            split2h(sc[2*jc][0],   sc[2*jc][1],   AH[0], AL[0]);
            split2h(sc[2*jc][2],   sc[2*jc][3],   AH[1], AL[1]);
            split2h(sc[2*jc+1][0], sc[2*jc+1][1], AH[2], AL[2]);
            split2h(sc[2*jc+1][2], sc[2*jc+1][3], AH[3], AL[3]);
            #pragma unroll
            for (int dp = 0; dp < 4; dp++) {
                uint32_t off = SWZ((uint32_t)((jc*16 + (vg & 1)*8 + vr) * 128 + (dp*16 + (vg >> 1)*8) * 2));
                uint32_t Vf[4];
                ldsm4t(Vf, stV + off);
                mma16816h(o[2*dp],   AH, &Vf[0]);
                mma16816h(o[2*dp],   AL, &Vf[0]);
                mma16816h(o[2*dp+1], AH, &Vf[2]);
                mma16816h(o[2*dp+1], AL, &Vf[2]);
            }
        }

        __syncthreads();
        if (c + 2 < nch) {
            load_kv_async(sb + AST0 + (uint32_t)s * ASTG, Kh, Vh, (c + 2) * 128, tid);
            asm volatile("cp.async.commit_group;" ::: "memory");
        }
    }

    // ---- epilogue: O/l -> bf16 hi/lo in (token, 768) layout ----
    const int b = bh / NH;
    const int h = bh - b * NH;
    const float inv0 = 1.f / l_[0];
    const float inv1 = 1.f / l_[1];
    const int q = q0 + m0 + (lane >> 2);
    const size_t tok0 = (size_t)(b * SEQ + q) * D_MODEL;
    const size_t tok1 = tok0 + 8 * D_MODEL;
    #pragma unroll
    for (int nj = 0; nj < 8; nj++) {
        const int dc = h * HEADD + nj*8 + (lane & 3)*2;
        uint32_t hi, lo;
        split2(o[nj][0] * inv0, o[nj][1] * inv0, hi, lo);
        *(uint32_t*)&g_oh[tok0 + dc] = hi;
        *(uint32_t*)&g_ol[tok0 + dc] = lo;
        split2(o[nj][2] * inv1, o[nj][3] * inv1, hi, lo);
        *(uint32_t*)&g_oh[tok1 + dc] = hi;
        *(uint32_t*)&g_ol[tok1 + dc] = lo;
    }
}

// ============================================================
extern "C" void kernel_launch(void* const* d_in, const int* in_sizes, int n_in,
                              void* d_out, int out_size)
{
    const float* x  = (const float*)d_in[0];   // (B,T,768)
    const float* W1 = (const float*)d_in[1];   // (2304,768)
    const float* b1 = (const float*)d_in[2];
    const float* W2 = (const float*)d_in[3];   // (768,768)
    const float* b2 = (const float*)d_in[4];
    float* out = (float*)d_out;

    __nv_bfloat16 *p_xh, *p_xl, *p_w1h, *p_w1l, *p_w2h, *p_w2l, *p_oh, *p_ol;
    cudaGetSymbolAddress((void**)&p_xh,  g_xh);
    cudaGetSymbolAddress((void**)&p_xl,  g_xl);
    cudaGetSymbolAddress((void**)&p_w1h, g_w1h);
    cudaGetSymbolAddress((void**)&p_w1l, g_w1l);
    cudaGetSymbolAddress((void**)&p_w2h, g_w2h);
    cudaGetSymbolAddress((void**)&p_w2l, g_w2l);
    cudaGetSymbolAddress((void**)&p_oh,  g_oh);
    cudaGetSymbolAddress((void**)&p_ol,  g_ol);

    cudaFuncSetAttribute(gemm_mma<0>, cudaFuncAttributeMaxDynamicSharedMemorySize, SMEM_GEMM);
    cudaFuncSetAttribute(gemm_mma<1>, cudaFuncAttributeMaxDynamicSharedMemorySize, SMEM_GEMM);
    cudaFuncSetAttribute(attn_mma,    cudaFuncAttributeMaxDynamicSharedMemorySize, SMEM_ATTN);

    convert_split<<<(M_TOK*D_MODEL)/1024, 256>>>(x,  p_xh,  p_xl,  M_TOK*D_MODEL);
    convert_split<<<(N_QKV*D_MODEL)/1024, 256>>>(W1, p_w1h, p_w1l, N_QKV*D_MODEL);
    convert_split<<<(D_MODEL*D_MODEL)/1024, 256>>>(W2, p_w2h, p_w2l, D_MODEL*D_MODEL);

    // 1) QKV projection -> fp16 q(hi,lo, scaled 1/8), k hi, v hi
    gemm_mma<0><<<dim3(N_QKV/128, M_TOK/128), 256, SMEM_GEMM>>>(
        p_xh, p_xl, p_w1h, p_w1l, b1, nullptr, N_QKV);

    // 2) fp16 2-pass tensor-core causal flash attention -> bf16 hi/lo O
    attn_mma<<<dim3(SEQ/128, BATCH*NH), 256, SMEM_ATTN>>>();

    // 3) output projection (bf16x3)
    gemm_mma<1><<<dim3(D_MODEL/128, M_TOK/128), 256, SMEM_GEMM>>>(
        p_oh, p_ol, p_w2h, p_w2l, b2, out, D_MODEL);
}

// round 6
// speedup vs baseline: 4.8473x; 1.2334x over previous
#include <cuda_runtime.h>
#include <cuda_bf16.h>
#include <cuda_fp16.h>
#include <cstdint>

#define D_MODEL 768
#define NH      12
#define HEADD   64
#define BATCH   2
#define SEQ     2048
#define M_TOK   (BATCH*SEQ)   // 4096
#define N_QKV   (3*D_MODEL)   // 2304

// ============================================================
// helpers
// ============================================================
__device__ __forceinline__ uint32_t smem_u32(const void* p) {
    uint32_t a;
    asm("{ .reg .u64 t; cvta.to.shared.u64 t, %1; cvt.u32.u64 %0, t; }" : "=r"(a) : "l"(p));
    return a;
}

__device__ __forceinline__ void ldsm4(uint32_t* r, uint32_t addr) {
    asm volatile("ldmatrix.sync.aligned.m8n8.x4.shared.b16 {%0,%1,%2,%3}, [%4];"
        : "=r"(r[0]), "=r"(r[1]), "=r"(r[2]), "=r"(r[3]) : "r"(addr));
}
__device__ __forceinline__ void ldsm4t(uint32_t* r, uint32_t addr) {
    asm volatile("ldmatrix.sync.aligned.m8n8.x4.trans.shared.b16 {%0,%1,%2,%3}, [%4];"
        : "=r"(r[0]), "=r"(r[1]), "=r"(r[2]), "=r"(r[3]) : "r"(addr));
}

__device__ __forceinline__ void mma16816h(float* c, const uint32_t* a, const uint32_t* b) {
    asm volatile(
        "mma.sync.aligned.m16n8k16.row.col.f32.f16.f16.f32 "
        "{%0,%1,%2,%3}, {%4,%5,%6,%7}, {%8,%9}, {%0,%1,%2,%3};"
        : "+f"(c[0]), "+f"(c[1]), "+f"(c[2]), "+f"(c[3])
        : "r"(a[0]), "r"(a[1]), "r"(a[2]), "r"(a[3]), "r"(b[0]), "r"(b[1]));
}

#define SWZ(off) ((off) ^ (((off) >> 3) & 0x70))

// split two fp32 into packed fp16 hi pair + lo pair
__device__ __forceinline__ void split2h(float a, float b, uint32_t& hi, uint32_t& lo) {
    __half2 h2 = __floats2half2_rn(a, b);
    hi = *(uint32_t*)&h2;
    float2 hf = __half22float2(h2);
    __half2 l2 = __floats2half2_rn(a - hf.x, b - hf.y);
    lo = *(uint32_t*)&l2;
}

// ---- scratch (device globals; no allocations allowed) ----
__device__ __align__(16) __half g_xh[(size_t)M_TOK*D_MODEL];
__device__ __align__(16) __half g_xl[(size_t)M_TOK*D_MODEL];
__device__ __align__(16) __half g_w1h[(size_t)N_QKV*D_MODEL];
__device__ __align__(16) __half g_w2h[(size_t)D_MODEL*D_MODEL];
__device__ __align__(16) __half g_qh[(size_t)BATCH*NH*SEQ*HEADD];
__device__ __align__(16) __half g_ql[(size_t)BATCH*NH*SEQ*HEADD];
__device__ __align__(16) __half g_kh[(size_t)BATCH*NH*SEQ*HEADD];
__device__ __align__(16) __half g_vh[(size_t)BATCH*NH*SEQ*HEADD];
__device__ __align__(16) __half g_oh[(size_t)M_TOK*D_MODEL];
__device__ __align__(16) __half g_ol[(size_t)M_TOK*D_MODEL];

// ============================================================
// fp32 -> (fp16 hi, fp16 lo) split / fp32 -> fp16
// ============================================================
__global__ __launch_bounds__(256)
void convert_split_h(const float* __restrict__ src,
                     __half* __restrict__ hi, __half* __restrict__ lo, int n)
{
    int i = (blockIdx.x * blockDim.x + threadIdx.x) * 4;
    if (i >= n) return;
    float4 v = *(const float4*)(src + i);
    uint32_t h0, l0, h1, l1;
    split2h(v.x, v.y, h0, l0);
    split2h(v.z, v.w, h1, l1);
    *(uint32_t*)(hi + i)     = h0;
    *(uint32_t*)(hi + i + 2) = h1;
    *(uint32_t*)(lo + i)     = l0;
    *(uint32_t*)(lo + i + 2) = l1;
}

__global__ __launch_bounds__(256)
void convert_h(const float* __restrict__ src, __half* __restrict__ dst, int n)
{
    int i = (blockIdx.x * blockDim.x + threadIdx.x) * 4;
    if (i >= n) return;
    float4 v = *(const float4*)(src + i);
    __half2 a = __floats2half2_rn(v.x, v.y);
    __half2 b = __floats2half2_rn(v.z, v.w);
    *(uint32_t*)(dst + i)     = *(uint32_t*)&a;
    *(uint32_t*)(dst + i + 2) = *(uint32_t*)&b;
}

// ============================================================
// fp16x2 GEMM via mma.sync: C = (Ah+Al) * Bh^T + bias
// CTA tile 128x128, 8 warps, 2-stage cp.async, 2 CTAs/SM.
// MODE 0: emit fp16 q hi/lo (scaled 1/8), k, v.  MODE 1: fp32 C.
// ============================================================
static constexpr int GBK     = 64;
static constexpr int NCH     = D_MODEL / GBK;    // 12
static constexpr int TILE_B  = 128 * 128;        // 16 KB
static constexpr int STAGE_B = 3 * TILE_B;       // 48 KB: Ah, Al, Bh
static constexpr int SMEM_GEMM = 2 * STAGE_B;    // 96 KB

__device__ __forceinline__ void load_tile_async(uint32_t smem_tile, const __half* g,
                                                int row0, int k0, int tid)
{
    #pragma unroll
    for (int i = 0; i < 4; i++) {
        int u  = tid + i * 256;
        int r  = u >> 3;
        int cu = u & 7;
        uint32_t dst = smem_tile + SWZ((uint32_t)(r * 128 + cu * 16));
        const void* src = g + (size_t)(row0 + r) * D_MODEL + k0 + cu * 8;
        asm volatile("cp.async.cg.shared.global [%0], [%1], 16;" :: "r"(dst), "l"(src) : "memory");
    }
}

template<int MODE>
__global__ __launch_bounds__(256, 2)
void gemm_mma(const __half* __restrict__ Ah, const __half* __restrict__ Al,
              const __half* __restrict__ Bh,
              const float* __restrict__ bias, float* __restrict__ C, int N)
{
    extern __shared__ __align__(1024) char smem[];
    const uint32_t sb = smem_u32(smem);
    const int tid  = threadIdx.x;
    const int wid  = tid >> 5;
    const int lane = tid & 31;
    const int wm   = wid & 1;
    const int wn   = wid >> 1;
    const int row0 = blockIdx.y * 128;
    const int col0 = blockIdx.x * 128;

    float acc[4][4][4] = {};

    const int aRow = wm * 64 + (lane & 15);
    const uint32_t xr = (uint32_t)((aRow & 7) << 4);
    const int aHalf = lane >> 4;
    const int bN = wn * 32 + (lane & 7) + ((lane >> 4) << 3);
    const uint32_t xn = (uint32_t)((lane & 7) << 4);
    const int bKb = ((lane >> 3) & 1) * 16;

    auto stage_addr = [&](int s) { return sb + (uint32_t)s * STAGE_B; };
    {
        uint32_t st = stage_addr(0);
        load_tile_async(st + 0*TILE_B, Ah, row0, 0, tid);
        load_tile_async(st + 1*TILE_B, Al, row0, 0, tid);
        load_tile_async(st + 2*TILE_B, Bh, col0, 0, tid);
        asm volatile("cp.async.commit_group;" ::: "memory");
        st = stage_addr(1);
        load_tile_async(st + 0*TILE_B, Ah, row0, GBK, tid);
        load_tile_async(st + 1*TILE_B, Al, row0, GBK, tid);
        load_tile_async(st + 2*TILE_B, Bh, col0, GBK, tid);
        asm volatile("cp.async.commit_group;" ::: "memory");
    }

    for (int c = 0; c < NCH; c++) {
        const int s = c & 1;
        if (c < NCH - 1) asm volatile("cp.async.wait_group 1;" ::: "memory");
        else             asm volatile("cp.async.wait_group 0;" ::: "memory");
        __syncthreads();

        const uint32_t st   = stage_addr(s);
        const uint32_t stAh = st;
        const uint32_t stAl = st + TILE_B;
        const uint32_t stBh = st + 2*TILE_B;

        #pragma unroll
        for (int ks = 0; ks < 4; ks++) {
            const uint32_t aKx = (uint32_t)((ks*32 + aHalf*16)) ^ xr;
            const uint32_t bKx = (uint32_t)((ks*32 + bKb)) ^ xn;

            uint32_t Afh[4][4], Afl[4][4], Bfh[2][4];
            #pragma unroll
            for (int mi = 0; mi < 4; mi++) {
                uint32_t off = (uint32_t)((aRow + mi*16) * 128) + aKx;
                ldsm4(Afh[mi], stAh + off);
                ldsm4(Afl[mi], stAl + off);
            }
            #pragma unroll
            for (int j2 = 0; j2 < 2; j2++) {
                uint32_t off = (uint32_t)((bN + j2*16) * 128) + bKx;
                ldsm4(Bfh[j2], stBh + off);
            }
            #pragma unroll
            for (int mi = 0; mi < 4; mi++) {
                #pragma unroll
                for (int nj = 0; nj < 4; nj++) {
                    const uint32_t* bh = &Bfh[nj >> 1][(nj & 1) * 2];
                    mma16816h(acc[mi][nj], Afh[mi], bh);
                    mma16816h(acc[mi][nj], Afl[mi], bh);
                }
            }
        }
        __syncthreads();

        if (c + 2 < NCH) {
            uint32_t st2 = stage_addr(s);
            int k0 = (c + 2) * GBK;
            load_tile_async(st2 + 0*TILE_B, Ah, row0, k0, tid);
            load_tile_async(st2 + 1*TILE_B, Al, row0, k0, tid);
            load_tile_async(st2 + 2*TILE_B, Bh, col0, k0, tid);
            asm volatile("cp.async.commit_group;" ::: "memory");
        }
    }

    #pragma unroll
    for (int mi = 0; mi < 4; mi++) {
        #pragma unroll
        for (int h2 = 0; h2 < 2; h2++) {
            const int m  = row0 + wm*64 + mi*16 + h2*8 + (lane >> 2);
            const int bb = m >> 11;
            const int t  = m & (SEQ - 1);
            #pragma unroll
            for (int nj = 0; nj < 4; nj++) {
                const int f = col0 + wn*32 + nj*8 + (lane & 3)*2;
                float vx = acc[mi][nj][h2*2+0] + bias[f];
                float vy = acc[mi][nj][h2*2+1] + bias[f+1];
                if (MODE == 0) {
                    int which = (f >= 1536) ? 2 : (f >= 768 ? 1 : 0);
                    int cc = f - which * 768;
                    int h = cc >> 6, d = cc & 63;
                    size_t idx = (((size_t)(bb*NH + h))*SEQ + t)*HEADD + d;
                    if (which == 0) {
                        uint32_t hi, lo;
                        split2h(vx * 0.125f, vy * 0.125f, hi, lo);
                        *(uint32_t*)&g_qh[idx] = hi;
                        *(uint32_t*)&g_ql[idx] = lo;
                    } else {
                        __half2 hv = __floats2half2_rn(vx, vy);
                        __half* dst = (which == 1) ? g_kh : g_vh;
                        *(uint32_t*)&dst[idx] = *(uint32_t*)&hv;
                    }
                } else {
                    float2 v; v.x = vx; v.y = vy;
                    *(float2*)&C[(size_t)m * N + f] = v;
                }
            }
        }
    }
}

// ============================================================
// Tensor-core flash attention (causal), fp16 2-pass.
// Grid (16, 24): 128 queries per CTA per head, 8 warps.
// kv chunks of 128 rows, 2-stage cp.async pipeline.
// ============================================================
static constexpr int AQ_H  = 0;                  // Q hi: 16 KB
static constexpr int AQ_L  = 16384;              // Q lo
static constexpr int AST0  = 32768;              // stages: Kh(16KB), Vh(16KB)
static constexpr int ASTG  = 32768;
static constexpr int SMEM_ATTN = 32768 + 2*ASTG; // 96 KB

__device__ __forceinline__ void load_kv_async(uint32_t st, const __half* Kh,
                                              const __half* Vh, int kc, int tid)
{
    #pragma unroll
    for (int i = 0; i < 4; i++) {
        int u  = tid + i * 256;
        int r  = u >> 3;
        int cu = u & 7;
        uint32_t dsw = SWZ((uint32_t)(r * 128 + cu * 16));
        size_t src = (size_t)(kc + r) * HEADD + cu * 8;
        asm volatile("cp.async.cg.shared.global [%0], [%1], 16;" :: "r"(st + dsw),         "l"((const void*)(Kh + src)) : "memory");
        asm volatile("cp.async.cg.shared.global [%0], [%1], 16;" :: "r"(st + 16384 + dsw), "l"((const void*)(Vh + src)) : "memory");
    }
}

__global__ __launch_bounds__(256, 1)
void attn_mma()
{
    extern __shared__ __align__(1024) char smem[];
    const uint32_t sb = smem_u32(smem);
    const int tid  = threadIdx.x;
    const int wid  = tid >> 5;
    const int lane = tid & 31;
    const int bh   = blockIdx.y;
    const int qt   = gridDim.x - 1 - blockIdx.x;   // heavy CTAs first
    const int q0   = qt * 128;
    const int m0   = wid * 16;
    const int nch  = qt + 1;

    const size_t hoff = (size_t)bh * SEQ * HEADD;
    const __half* Qh = g_qh + hoff;
    const __half* Ql = g_ql + hoff;
    const __half* Kh = g_kh + hoff;
    const __half* Vh = g_vh + hoff;

    #pragma unroll
    for (int i = 0; i < 4; i++) {
        int u  = tid + i * 256;
        int r  = u >> 3;
        int cu = u & 7;
        uint32_t dsw = SWZ((uint32_t)(r * 128 + cu * 16));
        size_t src = (size_t)(q0 + r) * HEADD + cu * 8;
        asm volatile("cp.async.cg.shared.global [%0], [%1], 16;" :: "r"(sb + AQ_H + dsw), "l"((const void*)(Qh + src)) : "memory");
        asm volatile("cp.async.cg.shared.global [%0], [%1], 16;" :: "r"(sb + AQ_L + dsw), "l"((const void*)(Ql + src)) : "memory");
    }
    load_kv_async(sb + AST0, Kh, Vh, 0, tid);
    asm volatile("cp.async.commit_group;" ::: "memory");
    load_kv_async(sb + AST0 + ASTG, Kh, Vh, 128, tid);
    asm volatile("cp.async.commit_group;" ::: "memory");

    uint32_t QfH[4][4], QfL[4][4];
    float o[8][4] = {};
    float m_[2] = {-1e30f, -1e30f};
    float l_[2] = {0.f, 0.f};

    const uint32_t aoff0 = (uint32_t)((m0 + (lane & 15)) * 128);
    const int aHalf = (lane >> 4) * 16;
    const int krow = (lane & 7) + ((lane >> 4) << 3);
    const int kcb  = ((lane >> 3) & 1) * 16;
    const int vg   = lane >> 3;
    const int vr   = lane & 7;

    for (int c = 0; c < nch; c++) {
        const int s = c & 1;
        if (c < nch - 1) asm volatile("cp.async.wait_group 1;" ::: "memory");
        else             asm volatile("cp.async.wait_group 0;" ::: "memory");
        __syncthreads();

        if (c == 0) {
            #pragma unroll
            for (int kc = 0; kc < 4; kc++) {
                uint32_t off = SWZ(aoff0 + (uint32_t)(kc*32 + aHalf));
                ldsm4(QfH[kc], sb + AQ_H + off);
                ldsm4(QfL[kc], sb + AQ_L + off);
            }
        }

        const uint32_t stK = sb + AST0 + (uint32_t)s * ASTG;
        const uint32_t stV = stK + 16384;

        // ---- S = (Qh+Ql) K^T ----
        float sc[16][4];
        #pragma unroll
        for (int nj = 0; nj < 16; nj++) { sc[nj][0]=0.f; sc[nj][1]=0.f; sc[nj][2]=0.f; sc[nj][3]=0.f; }
        #pragma unroll
        for (int kc = 0; kc < 4; kc++) {
            #pragma unroll
            for (int np = 0; np < 8; np++) {
                uint32_t off = SWZ((uint32_t)((np*16 + krow) * 128 + kc*32 + kcb));
                uint32_t Bf[4];
                ldsm4(Bf, stK + off);
                mma16816h(sc[2*np],   QfH[kc], &Bf[0]);
                mma16816h(sc[2*np],   QfL[kc], &Bf[0]);
                mma16816h(sc[2*np+1], QfH[kc], &Bf[2]);
                mma16816h(sc[2*np+1], QfL[kc], &Bf[2]);
            }
        }

        if (c == nch - 1) {
            const int qr0 = q0 + m0 + (lane >> 2);
            const int cb  = c*128 + (lane & 3)*2;
            #pragma unroll
            for (int nj = 0; nj < 16; nj++) {
                int col = cb + nj*8;
                if (col     > qr0)     sc[nj][0] = -1e30f;
                if (col + 1 > qr0)     sc[nj][1] = -1e30f;
                if (col     > qr0 + 8) sc[nj][2] = -1e30f;
                if (col + 1 > qr0 + 8) sc[nj][3] = -1e30f;
            }
        }

        #pragma unroll
        for (int rr = 0; rr < 2; rr++) {
            float mx = -1e30f;
            #pragma unroll
            for (int nj = 0; nj < 16; nj++)
                mx = fmaxf(mx, fmaxf(sc[nj][2*rr], sc[nj][2*rr+1]));
            mx = fmaxf(mx, __shfl_xor_sync(0xffffffffu, mx, 1));
            mx = fmaxf(mx, __shfl_xor_sync(0xffffffffu, mx, 2));
            float mn   = fmaxf(m_[rr], mx);
            float corr = __expf(m_[rr] - mn);
            float rs = 0.f;
            #pragma unroll
            for (int nj = 0; nj < 16; nj++) {
                float p0 = __expf(sc[nj][2*rr]   - mn);
                float p1 = __expf(sc[nj][2*rr+1] - mn);
                sc[nj][2*rr]   = p0;
                sc[nj][2*rr+1] = p1;
                rs += p0 + p1;
            }
            rs += __shfl_xor_sync(0xffffffffu, rs, 1);
            rs += __shfl_xor_sync(0xffffffffu, rs, 2);
            l_[rr] = l_[rr] * corr + rs;
            m_[rr] = mn;
            #pragma unroll
            for (int nj = 0; nj < 8; nj++) {
                o[nj][2*rr]   *= corr;
                o[nj][2*rr+1] *= corr;
            }
        }

        // ---- O += (Ph+Pl) V ----
        #pragma unroll
        for (int jc = 0; jc < 8; jc++) {
            uint32_t AH[4], AL[4];
            split2h(sc[2*jc][0],   sc[2*jc][1],   AH[0], AL[0]);
            split2h(sc[2*jc][2],   sc[2*jc][3],   AH[1], AL[1]);
            split2h(sc[2*jc+1][0], sc[2*jc+1][1], AH[2], AL[2]);
            split2h(sc[2*jc+1][2], sc[2*jc+1][3], AH[3], AL[3]);
            #pragma unroll
            for (int dp = 0; dp < 4; dp++) {
                uint32_t off = SWZ((uint32_t)((jc*16 + (vg & 1)*8 + vr) * 128 + (dp*16 + (vg >> 1)*8) * 2));
                uint32_t Vf[4];
                ldsm4t(Vf, stV + off);
                mma16816h(o[2*dp],   AH, &Vf[0]);
                mma16816h(o[2*dp],   AL, &Vf[0]);
                mma16816h(o[2*dp+1], AH, &Vf[2]);
                mma16816h(o[2*dp+1], AL, &Vf[2]);
            }
        }

        __syncthreads();
        if (c + 2 < nch) {
            load_kv_async(sb + AST0 + (uint32_t)s * ASTG, Kh, Vh, (c + 2) * 128, tid);
            asm volatile("cp.async.commit_group;" ::: "memory");
        }
    }

    // ---- epilogue: O/l -> fp16 hi/lo in (token, 768) layout ----
    const int b = bh / NH;
    const int h = bh - b * NH;
    const float inv0 = 1.f / l_[0];
    const float inv1 = 1.f / l_[1];
    const int q = q0 + m0 + (lane >> 2);
    const size_t tok0 = (size_t)(b * SEQ + q) * D_MODEL;
    const size_t tok1 = tok0 + 8 * D_MODEL;
    #pragma unroll
    for (int nj = 0; nj < 8; nj++) {
        const int dc = h * HEADD + nj*8 + (lane & 3)*2;
        uint32_t hi, lo;
        split2h(o[nj][0] * inv0, o[nj][1] * inv0, hi, lo);
        *(uint32_t*)&g_oh[tok0 + dc] = hi;
        *(uint32_t*)&g_ol[tok0 + dc] = lo;
        split2h(o[nj][2] * inv1, o[nj][3] * inv1, hi, lo);
        *(uint32_t*)&g_oh[tok1 + dc] = hi;
        *(uint32_t*)&g_ol[tok1 + dc] = lo;
    }
}

// ============================================================
extern "C" void kernel_launch(void* const* d_in, const int* in_sizes, int n_in,
                              void* d_out, int out_size)
{
    const float* x  = (const float*)d_in[0];   // (B,T,768)
    const float* W1 = (const float*)d_in[1];   // (2304,768)
    const float* b1 = (const float*)d_in[2];
    const float* W2 = (const float*)d_in[3];   // (768,768)
    const float* b2 = (const float*)d_in[4];
    float* out = (float*)d_out;

    __half *p_xh, *p_xl, *p_w1h, *p_w2h, *p_oh, *p_ol;
    cudaGetSymbolAddress((void**)&p_xh,  g_xh);
    cudaGetSymbolAddress((void**)&p_xl,  g_xl);
    cudaGetSymbolAddress((void**)&p_w1h, g_w1h);
    cudaGetSymbolAddress((void**)&p_w2h, g_w2h);
    cudaGetSymbolAddress((void**)&p_oh,  g_oh);
    cudaGetSymbolAddress((void**)&p_ol,  g_ol);

    cudaFuncSetAttribute(gemm_mma<0>, cudaFuncAttributeMaxDynamicSharedMemorySize, SMEM_GEMM);
    cudaFuncSetAttribute(gemm_mma<1>, cudaFuncAttributeMaxDynamicSharedMemorySize, SMEM_GEMM);
    cudaFuncSetAttribute(attn_mma,    cudaFuncAttributeMaxDynamicSharedMemorySize, SMEM_ATTN);

    convert_split_h<<<(M_TOK*D_MODEL)/1024, 256>>>(x,  p_xh, p_xl, M_TOK*D_MODEL);
    convert_h<<<(N_QKV*D_MODEL)/1024, 256>>>(W1, p_w1h, N_QKV*D_MODEL);
    convert_h<<<(D_MODEL*D_MODEL)/1024, 256>>>(W2, p_w2h, D_MODEL*D_MODEL);

    // 1) QKV projection (fp16x2) -> q hi/lo (scaled 1/8), k, v
    gemm_mma<0><<<dim3(N_QKV/128, M_TOK/128), 256, SMEM_GEMM>>>(
        p_xh, p_xl, p_w1h, b1, nullptr, N_QKV);

    // 2) fp16 2-pass tensor-core causal flash attention -> fp16 hi/lo O
    attn_mma<<<dim3(SEQ/128, BATCH*NH), 256, SMEM_ATTN>>>();

    // 3) output projection (fp16x2)
    gemm_mma<1><<<dim3(D_MODEL/128, M_TOK/128), 256, SMEM_GEMM>>>(
        p_oh, p_ol, p_w2h, b2, out, D_MODEL);
}